// round 2
// baseline (speedup 1.0000x reference)
#include <cuda_runtime.h>
#include <cuda_bf16.h>
#include <cstdint>

// Problem constants
#define NB      2048
#define NA      64
#define NATOMS  (NB*NA)      // 131072
#define AEV     384
#define N0      160
#define N1      128
#define N2      96
#define NTYPES  4
#define TILE    64
#define MAXTILES 2056

// -------- device scratch (no allocations allowed) --------
__device__ int   g_is64;
__device__ int   g_counts[NTYPES];
__device__ int   g_cursor[NTYPES];
__device__ int   g_offsets[NTYPES];
__device__ int   g_ntiles;
__device__ int   g_tile_type[MAXTILES];
__device__ int   g_tile_start[MAXTILES];
__device__ int   g_tile_len[MAXTILES];
__device__ int   g_perm[NATOMS];
__device__ float g_atom_e[NATOMS];

__device__ __forceinline__ float celu_f(float x) {
    // jax.nn.celu(x, alpha=0.1) = x>0 ? x : 0.1*(exp(x/0.1)-1)
    return x > 0.f ? x : 0.1f * expm1f(10.f * x);
}

// species accessor: raw buffer viewed as int32 words; if underlying dtype is
// int64 (little-endian, small non-negative values) the value lives at word 2*i.
__device__ __forceinline__ int get_sp(const int* __restrict__ raw, int i, int is64) {
    return is64 ? raw[2 * i] : raw[i];
}

// -------- dtype probe + reset --------
__global__ void k_detect(const int* __restrict__ sp_raw) {
    if (threadIdx.x == 0) {
        int odd_nonzero = 0;
        #pragma unroll
        for (int i = 1; i < 64; i += 2) odd_nonzero |= (sp_raw[i] != 0);
        g_is64 = odd_nonzero ? 0 : 1;
    }
    if (threadIdx.x < NTYPES) { g_counts[threadIdx.x] = 0; g_cursor[threadIdx.x] = 0; }
}

__global__ void k_count(const int* __restrict__ sp) {
    __shared__ int c[NTYPES];
    if (threadIdx.x < NTYPES) c[threadIdx.x] = 0;
    __syncthreads();
    int i = blockIdx.x * blockDim.x + threadIdx.x;
    if (i < NATOMS) {
        g_atom_e[i] = 0.f;
        int t = get_sp(sp, i, g_is64);
        if ((unsigned)t < NTYPES) atomicAdd(&c[t], 1);
    }
    __syncthreads();
    if (threadIdx.x < NTYPES && c[threadIdx.x]) atomicAdd(&g_counts[threadIdx.x], c[threadIdx.x]);
}

__global__ void k_build() {
    if (blockIdx.x == 0 && threadIdx.x == 0) {
        int off = 0, nt = 0;
        for (int t = 0; t < NTYPES; t++) {
            g_offsets[t] = off;
            int c = g_counts[t];
            for (int j = 0; j < c && nt < MAXTILES; j += TILE) {
                g_tile_type[nt]  = t;
                g_tile_start[nt] = off + j;
                g_tile_len[nt]   = (c - j) < TILE ? (c - j) : TILE;
                nt++;
            }
            off += c;
        }
        g_ntiles = nt;
    }
}

__global__ void k_scatter(const int* __restrict__ sp) {
    __shared__ int base[NTYPES];
    __shared__ int lc[NTYPES];
    if (threadIdx.x < NTYPES) lc[threadIdx.x] = 0;
    __syncthreads();
    int i = blockIdx.x * blockDim.x + threadIdx.x;
    int t = -1, r = 0;
    if (i < NATOMS) {
        t = get_sp(sp, i, g_is64);
        if ((unsigned)t < NTYPES) r = atomicAdd(&lc[t], 1); else t = -1;
    }
    __syncthreads();
    if (threadIdx.x < NTYPES)
        base[threadIdx.x] = lc[threadIdx.x] ? atomicAdd(&g_cursor[threadIdx.x], lc[threadIdx.x]) : 0;
    __syncthreads();
    if (t >= 0) g_perm[g_offsets[t] + base[t] + r] = i;
}

// -------- fused MLP over a 64-atom same-type tile --------
// smem arena (floats):
//   H0 @ 0          : 64*161 = 10304
//   H1 @ 10304      : 64*129 = 8256   (XB, 64*33=2112, overlaps H1; XB dead before L1)
//   WB @ 18560      : 32*160 = 5120
//   H2 @ 0          : 64*97           (overlaps H0; H0 dead after L1)
// total 23680 floats = 94720 B
#define SM_FLOATS 23680
#define H0_OFF 0
#define H0_S   161
#define H1_OFF 10304
#define H1_S   129
#define XB_OFF 10304
#define XB_S   33
#define WB_OFF 18560
#define H2_OFF 0
#define H2_S   97

__global__ __launch_bounds__(256, 2)
void k_mlp(const float* __restrict__ aev,
           const float* __restrict__ W0, const float* __restrict__ b0,
           const float* __restrict__ W1, const float* __restrict__ b1,
           const float* __restrict__ W2, const float* __restrict__ b2,
           const float* __restrict__ W3, const float* __restrict__ b3)
{
    int bt = blockIdx.x;
    if (bt >= g_ntiles) return;

    extern __shared__ float sm[];
    float* H0 = sm + H0_OFF;
    float* H1 = sm + H1_OFF;
    float* XB = sm + XB_OFF;
    float* WB = sm + WB_OFF;
    float* H2 = sm + H2_OFF;
    __shared__ int sIdx[TILE];

    const int tid = threadIdx.x;
    const int t      = g_tile_type[bt];
    const int gstart = g_tile_start[bt];
    const int len    = g_tile_len[bt];

    if (tid < TILE) sIdx[tid] = (tid < len) ? g_perm[gstart + tid] : -1;
    __syncthreads();

    const int gn = tid & 15;   // neuron group
    const int ga = tid >> 4;   // atom group
    const int a0 = ga * 4;

    // ===== Layer 0: 384 -> 160, TN = 10 =====
    {
        float acc[4][10];
        #pragma unroll
        for (int i = 0; i < 4; i++)
            #pragma unroll
            for (int j = 0; j < 10; j++) acc[i][j] = 0.f;

        const float* Wg0 = W0 + (size_t)t * AEV * N0;
        for (int kc = 0; kc < AEV; kc += 32) {
            // stage X chunk (gathered rows)
            for (int idx = tid; idx < TILE * 32; idx += 256) {
                int a = idx >> 5, kk = idx & 31;
                int gi = sIdx[a];
                XB[a * XB_S + kk] = (gi >= 0) ? aev[(size_t)gi * AEV + kc + kk] : 0.f;
            }
            // stage W chunk [32][160]
            const float* Wg = Wg0 + (size_t)kc * N0;
            for (int idx = tid; idx < 32 * N0; idx += 256) WB[idx] = Wg[idx];
            __syncthreads();

            #pragma unroll
            for (int kk = 0; kk < 32; kk++) {
                float xv[4];
                #pragma unroll
                for (int i = 0; i < 4; i++) xv[i] = XB[(a0 + i) * XB_S + kk];
                #pragma unroll
                for (int j = 0; j < 10; j++) {
                    float w = WB[kk * N0 + gn * 10 + j];
                    #pragma unroll
                    for (int i = 0; i < 4; i++) acc[i][j] = fmaf(xv[i], w, acc[i][j]);
                }
            }
            __syncthreads();
        }
        #pragma unroll
        for (int j = 0; j < 10; j++) {
            float bb = b0[t * N0 + gn * 10 + j];
            #pragma unroll
            for (int i = 0; i < 4; i++)
                H0[(a0 + i) * H0_S + gn * 10 + j] = celu_f(acc[i][j] + bb);
        }
        __syncthreads();
    }

    // ===== Layer 1: 160 -> 128, TN = 8 =====
    {
        float acc[4][8];
        #pragma unroll
        for (int i = 0; i < 4; i++)
            #pragma unroll
            for (int j = 0; j < 8; j++) acc[i][j] = 0.f;

        const float* Wg1 = W1 + (size_t)t * N0 * N1;
        for (int kc = 0; kc < N0; kc += 32) {
            const float* Wg = Wg1 + (size_t)kc * N1;
            for (int idx = tid; idx < 32 * N1; idx += 256) WB[idx] = Wg[idx];
            __syncthreads();

            #pragma unroll
            for (int kk = 0; kk < 32; kk++) {
                float xv[4];
                #pragma unroll
                for (int i = 0; i < 4; i++) xv[i] = H0[(a0 + i) * H0_S + kc + kk];
                #pragma unroll
                for (int j = 0; j < 8; j++) {
                    float w = WB[kk * N1 + gn * 8 + j];
                    #pragma unroll
                    for (int i = 0; i < 4; i++) acc[i][j] = fmaf(xv[i], w, acc[i][j]);
                }
            }
            __syncthreads();
        }
        #pragma unroll
        for (int j = 0; j < 8; j++) {
            float bb = b1[t * N1 + gn * 8 + j];
            #pragma unroll
            for (int i = 0; i < 4; i++)
                H1[(a0 + i) * H1_S + gn * 8 + j] = celu_f(acc[i][j] + bb);
        }
        __syncthreads();
    }

    // ===== Layer 2: 128 -> 96, TN = 6 =====
    {
        float acc[4][6];
        #pragma unroll
        for (int i = 0; i < 4; i++)
            #pragma unroll
            for (int j = 0; j < 6; j++) acc[i][j] = 0.f;

        const float* Wg2 = W2 + (size_t)t * N1 * N2;
        for (int kc = 0; kc < N1; kc += 32) {
            const float* Wg = Wg2 + (size_t)kc * N2;
            for (int idx = tid; idx < 32 * N2; idx += 256) WB[idx] = Wg[idx];
            __syncthreads();

            #pragma unroll
            for (int kk = 0; kk < 32; kk++) {
                float xv[4];
                #pragma unroll
                for (int i = 0; i < 4; i++) xv[i] = H1[(a0 + i) * H1_S + kc + kk];
                #pragma unroll
                for (int j = 0; j < 6; j++) {
                    float w = WB[kk * N2 + gn * 6 + j];
                    #pragma unroll
                    for (int i = 0; i < 4; i++) acc[i][j] = fmaf(xv[i], w, acc[i][j]);
                }
            }
            __syncthreads();
        }
        #pragma unroll
        for (int j = 0; j < 6; j++) {
            float bb = b2[t * N2 + gn * 6 + j];
            #pragma unroll
            for (int i = 0; i < 4; i++)
                H2[(a0 + i) * H2_S + gn * 6 + j] = celu_f(acc[i][j] + bb);
        }
        __syncthreads();
    }

    // ===== Layer 3: 96 -> 1 =====
    if (tid < TILE && tid < len) {
        const float* w3 = W3 + t * N2;
        float e = b3[t];
        #pragma unroll 8
        for (int k = 0; k < N2; k++) e = fmaf(H2[tid * H2_S + k], w3[k], e);
        g_atom_e[sIdx[tid]] = e;
    }
}

// -------- output assembly: species (optional) + per-molecule reduce --------
__global__ void k_finalize(const int* __restrict__ sp,
                           float* __restrict__ out_head,   // may be null
                           float* __restrict__ out_e)
{
    int b  = blockIdx.x;   // 2048 molecules
    int tx = threadIdx.x;  // 64 atoms
    int i  = b * NA + tx;
    float e = g_atom_e[i];
    if (out_head) out_head[i] = (float)get_sp(sp, i, g_is64);
    #pragma unroll
    for (int o = 16; o > 0; o >>= 1) e += __shfl_down_sync(0xffffffffu, e, o);
    __shared__ float s2[2];
    if ((tx & 31) == 0) s2[tx >> 5] = e;
    __syncthreads();
    if (tx == 0) out_e[b] = s2[0] + s2[1];
}

extern "C" void kernel_launch(void* const* d_in, const int* in_sizes, int n_in,
                              void* d_out, int out_size)
{
    const int*   sp  = (const int*)d_in[0];   // int32 or int64, probed on device
    const float* aev = (const float*)d_in[1];
    const float* W0 = (const float*)d_in[2];
    const float* b0 = (const float*)d_in[3];
    const float* W1 = (const float*)d_in[4];
    const float* b1 = (const float*)d_in[5];
    const float* W2 = (const float*)d_in[6];
    const float* b2 = (const float*)d_in[7];
    const float* W3 = (const float*)d_in[8];
    const float* b3 = (const float*)d_in[9];

    float* out = (float*)d_out;
    float* out_head;
    float* out_e;
    if (out_size == NB) {                // energies only
        out_head = nullptr;
        out_e    = out;
    } else {                             // (species, energies) concatenated
        out_head = out;
        out_e    = out + (out_size - NB);
    }

    k_detect <<<1, 32>>>(sp);
    k_count  <<<NATOMS / 256, 256>>>(sp);
    k_build  <<<1, 1>>>();
    k_scatter<<<NATOMS / 256, 256>>>(sp);

    cudaFuncSetAttribute(k_mlp, cudaFuncAttributeMaxDynamicSharedMemorySize,
                         SM_FLOATS * (int)sizeof(float));
    k_mlp<<<MAXTILES - 4, 256, SM_FLOATS * sizeof(float)>>>(
        aev, W0, b0, W1, b1, W2, b2, W3, b3);

    k_finalize<<<NB, NA>>>(sp, out_head, out_e);
}

// round 4
// speedup vs baseline: 2.1309x; 2.1309x over previous
#include <cuda_runtime.h>
#include <cuda_bf16.h>
#include <cstdint>

// ---------------- problem constants ----------------
#define NB      2048
#define NA      64
#define NATOMS  (NB*NA)
#define AEV     384
#define N0      160
#define N1      128
#define N2      96
#define NTYPES  4
#define TILE    128
#define MAXTILES 1040

// ---------------- device scratch ----------------
__device__ int   g_is64;
__device__ int   g_counts[NTYPES];
__device__ int   g_cursor[NTYPES];
__device__ int   g_offsets[NTYPES];
__device__ int   g_ntiles;
__device__ int   g_tile_type[MAXTILES];
__device__ int   g_tile_start[MAXTILES];
__device__ int   g_tile_len[MAXTILES];
__device__ int   g_perm[NATOMS];
__device__ float g_atom_e[NATOMS];

// pre-split weight images, [n][k] layout, padded strides (bytes): W0 208, W1 336, W2 272
__device__ char g_W0img[2][NTYPES][4][160 * 208];   // per 96-K chunk
__device__ char g_W1img[2][NTYPES][2][64 * 336];    // per 64-N half, K=160
__device__ char g_W2img[2][NTYPES][96 * 272];       // K=128

__device__ __forceinline__ float celu_f(float x) {
    return x > 0.f ? x : 0.1f * expm1f(10.f * x);
}
__device__ __forceinline__ int get_sp(const int* __restrict__ raw, int i, int is64) {
    return is64 ? raw[2 * i] : raw[i];
}
__device__ __forceinline__ uint32_t pack2(float a, float b) {
    __nv_bfloat16 ha = __float2bfloat16(a), hb = __float2bfloat16(b);
    return (uint32_t)__bfloat16_as_ushort(ha) | ((uint32_t)__bfloat16_as_ushort(hb) << 16);
}
__device__ __forceinline__ void split2(float a, float b, uint32_t& hi, uint32_t& lo) {
    __nv_bfloat16 ha = __float2bfloat16(a), hb = __float2bfloat16(b);
    float ra = a - __bfloat162float(ha), rb = b - __bfloat162float(hb);
    hi = (uint32_t)__bfloat16_as_ushort(ha) | ((uint32_t)__bfloat16_as_ushort(hb) << 16);
    lo = pack2(ra, rb);
}
__device__ __forceinline__ uint32_t smem_u32(const void* p) {
    uint32_t a;
    asm("{ .reg .u64 t; cvta.to.shared.u64 t, %1; cvt.u32.u64 %0, t; }" : "=r"(a) : "l"(p));
    return a;
}
__device__ __forceinline__ void ldm_x4(uint32_t* r, uint32_t addr) {
    asm volatile("ldmatrix.sync.aligned.m8n8.x4.shared.b16 {%0,%1,%2,%3}, [%4];"
                 : "=r"(r[0]), "=r"(r[1]), "=r"(r[2]), "=r"(r[3]) : "r"(addr));
}
__device__ __forceinline__ void mma_bf16(float* d, const uint32_t* a, const uint32_t* b) {
    asm volatile(
        "mma.sync.aligned.m16n8k16.row.col.f32.bf16.bf16.f32 "
        "{%0,%1,%2,%3},{%4,%5,%6,%7},{%8,%9},{%0,%1,%2,%3};"
        : "+f"(d[0]), "+f"(d[1]), "+f"(d[2]), "+f"(d[3])
        : "r"(a[0]), "r"(a[1]), "r"(a[2]), "r"(a[3]), "r"(b[0]), "r"(b[1]));
}

// ---------------- sorting pipeline ----------------
__global__ void k_detect(const int* __restrict__ sp_raw) {
    if (threadIdx.x == 0) {
        int odd_nonzero = 0;
        #pragma unroll
        for (int i = 1; i < 64; i += 2) odd_nonzero |= (sp_raw[i] != 0);
        g_is64 = odd_nonzero ? 0 : 1;
    }
    if (threadIdx.x < NTYPES) { g_counts[threadIdx.x] = 0; g_cursor[threadIdx.x] = 0; }
}

__global__ void k_count(const int* __restrict__ sp) {
    __shared__ int c[NTYPES];
    if (threadIdx.x < NTYPES) c[threadIdx.x] = 0;
    __syncthreads();
    int i = blockIdx.x * blockDim.x + threadIdx.x;
    if (i < NATOMS) {
        g_atom_e[i] = 0.f;
        int t = get_sp(sp, i, g_is64);
        if ((unsigned)t < NTYPES) atomicAdd(&c[t], 1);
    }
    __syncthreads();
    if (threadIdx.x < NTYPES && c[threadIdx.x]) atomicAdd(&g_counts[threadIdx.x], c[threadIdx.x]);
}

__global__ void k_build() {
    if (blockIdx.x == 0 && threadIdx.x == 0) {
        int off = 0, nt = 0;
        for (int t = 0; t < NTYPES; t++) {
            g_offsets[t] = off;
            int c = g_counts[t];
            for (int j = 0; j < c && nt < MAXTILES; j += TILE) {
                g_tile_type[nt]  = t;
                g_tile_start[nt] = off + j;
                g_tile_len[nt]   = (c - j) < TILE ? (c - j) : TILE;
                nt++;
            }
            off += c;
        }
        g_ntiles = nt;
    }
}

__global__ void k_scatter(const int* __restrict__ sp) {
    __shared__ int base[NTYPES];
    __shared__ int lc[NTYPES];
    if (threadIdx.x < NTYPES) lc[threadIdx.x] = 0;
    __syncthreads();
    int i = blockIdx.x * blockDim.x + threadIdx.x;
    int t = -1, r = 0;
    if (i < NATOMS) {
        t = get_sp(sp, i, g_is64);
        if ((unsigned)t < NTYPES) r = atomicAdd(&lc[t], 1); else t = -1;
    }
    __syncthreads();
    if (threadIdx.x < NTYPES)
        base[threadIdx.x] = lc[threadIdx.x] ? atomicAdd(&g_cursor[threadIdx.x], lc[threadIdx.x]) : 0;
    __syncthreads();
    if (t >= 0) g_perm[g_offsets[t] + base[t] + r] = i;
}

// ---------------- weight prep ----------------
#define PREP_W0 122880   // 4t * 4c * 160n * 48j
#define PREP_W1 40960    // 4t * 2h * 64n * 80j
#define PREP_W2 24576    // 4t * 96n * 64j
#define PREP_TOTAL (PREP_W0 + PREP_W1 + PREP_W2)

__global__ void k_prep(const float* __restrict__ W0, const float* __restrict__ W1,
                       const float* __restrict__ W2) {
    int idx = blockIdx.x * blockDim.x + threadIdx.x;
    if (idx < PREP_W0) {
        int t = idx / 30720, r = idx % 30720;
        int c = r / 7680;  r %= 7680;
        int n = r / 48, j = r % 48;
        int k0 = c * 96 + 2 * j;
        float v0 = W0[((size_t)t * AEV + k0)     * N0 + n];
        float v1 = W0[((size_t)t * AEV + k0 + 1) * N0 + n];
        uint32_t hi, lo; split2(v0, v1, hi, lo);
        int byte = n * 208 + j * 4;
        *(uint32_t*)(g_W0img[0][t][c] + byte) = hi;
        *(uint32_t*)(g_W0img[1][t][c] + byte) = lo;
    } else if (idx < PREP_W0 + PREP_W1) {
        int i2 = idx - PREP_W0;
        int t = i2 / 10240, r = i2 % 10240;
        int h = r / 5120;  r %= 5120;
        int n = r / 80, j = r % 80;
        int k0 = 2 * j;
        float v0 = W1[((size_t)t * N0 + k0)     * N1 + h * 64 + n];
        float v1 = W1[((size_t)t * N0 + k0 + 1) * N1 + h * 64 + n];
        uint32_t hi, lo; split2(v0, v1, hi, lo);
        int byte = n * 336 + j * 4;
        *(uint32_t*)(g_W1img[0][t][h] + byte) = hi;
        *(uint32_t*)(g_W1img[1][t][h] + byte) = lo;
    } else if (idx < PREP_TOTAL) {
        int i3 = idx - PREP_W0 - PREP_W1;
        int t = i3 / 6144, r = i3 % 6144;
        int n = r / 64, j = r % 64;
        int k0 = 2 * j;
        float v0 = W2[((size_t)t * N1 + k0)     * N2 + n];
        float v1 = W2[((size_t)t * N1 + k0 + 1) * N2 + n];
        uint32_t hi, lo; split2(v0, v1, hi, lo);
        int byte = n * 272 + j * 4;
        *(uint32_t*)(g_W2img[0][t] + byte) = hi;
        *(uint32_t*)(g_W2img[1][t] + byte) = lo;
    }
}

// ---------------- fused MLP (mma.sync bf16 split) ----------------
// SMEM arena (bytes):
#define H0H_OFF 0            // 128*336 = 43008
#define H0L_OFF 43008
#define XH_OFF  86016        // 128*208 = 26624
#define XL_OFF  112640
#define W0H_OFF 139264       // 160*208 = 33280
#define W0L_OFF 172544       // end 205824
#define W1H_OFF 86016        // 64*336 = 21504 (over X, L1)
#define W1L_OFF 107520       // end 129024
#define H1H_OFF 129024       // 128*272 = 34816 (over W0, L1 epilogue..L2)
#define H1L_OFF 163840       // end 198656
#define W2H_OFF 0            // 96*272 = 26112 (over H0, L2)
#define W2L_OFF 26112        // end 52224
#define SIDX_OFF 205824      // 512 B
#define SE_OFF   206336      // 512 B
#define BIAS_OFF 206848      // 482 floats
#define SM_TOTAL 208896

__global__ __launch_bounds__(256, 1)
void k_mlp_tc(const float* __restrict__ aev,
              const float* __restrict__ b0, const float* __restrict__ b1,
              const float* __restrict__ b2, const float* __restrict__ W3,
              const float* __restrict__ b3)
{
    int bt = blockIdx.x;
    if (bt >= g_ntiles) return;

    extern __shared__ char smem[];
    const uint32_t sb = smem_u32(smem);
    int*   sIdx  = (int*)(smem + SIDX_OFF);
    float* sE    = (float*)(smem + SE_OFF);
    float* sBias = (float*)(smem + BIAS_OFF);

    const int tid  = threadIdx.x;
    const int lane = tid & 31;
    const int w    = tid >> 5;
    const int mb   = (w & 3) * 32;   // warp M base (rows)
    const int nw   = (w >> 2);       // 0 or 1: warp N group

    const int t      = g_tile_type[bt];
    const int gstart = g_tile_start[bt];
    const int len    = g_tile_len[bt];

    if (tid < 128) {
        sIdx[tid] = (tid < len) ? g_perm[gstart + tid] : -1;
        sE[tid] = 0.f;
    }
    for (int i = tid; i < N0; i += 256) sBias[i] = b0[t * N0 + i];
    for (int i = tid; i < N1; i += 256) sBias[160 + i] = b1[t * N1 + i];
    for (int i = tid; i < N2; i += 256) { sBias[288 + i] = b2[t * N2 + i]; sBias[384 + i] = W3[t * N2 + i]; }
    if (tid == 0) sBias[480] = b3[t];
    __syncthreads();

    // lane offsets for ldmatrix (A: m16k16 quad; B: n16k16 quad), per stride
    const int arow = (lane & 7) + (lane & 8);
    const int akb  = (lane & 16) ? 16 : 0;
    const int brow = (lane & 7) + ((lane & 16) ? 8 : 0);
    const int bkb  = (lane & 8) ? 16 : 0;

    // ===================== LAYER 0: 384 -> 160 =====================
    float acc0[2][10][4];
    #pragma unroll
    for (int mt = 0; mt < 2; mt++)
        #pragma unroll
        for (int nt = 0; nt < 10; nt++)
            #pragma unroll
            for (int q = 0; q < 4; q++) acc0[mt][nt][q] = 0.f;

    const uint32_t aH0 = sb + XH_OFF + (mb + arow) * 208 + akb;
    const uint32_t aL0 = sb + XL_OFF + (mb + arow) * 208 + akb;
    const uint32_t bH0 = sb + W0H_OFF + (nw * 80 + brow) * 208 + bkb;
    const uint32_t bL0 = sb + W0L_OFF + (nw * 80 + brow) * 208 + bkb;

    for (int c = 0; c < 4; c++) {
        if (c) __syncthreads();
        // stage X chunk: row = tid/2, 48 cols per half-thread
        {
            int row  = tid >> 1;
            int col0 = (tid & 1) * 48;
            int gi   = sIdx[row];
            const float4* src = (const float4*)(aev + (size_t)(gi < 0 ? 0 : gi) * AEV + c * 96 + col0);
            char* dh = smem + XH_OFF + row * 208 + col0 * 2;
            char* dl = smem + XL_OFF + row * 208 + col0 * 2;
            #pragma unroll
            for (int i = 0; i < 12; i++) {
                float4 v = (gi >= 0) ? src[i] : make_float4(0.f, 0.f, 0.f, 0.f);
                uint32_t h0, l0, h1, l1;
                split2(v.x, v.y, h0, l0);
                split2(v.z, v.w, h1, l1);
                *(uint32_t*)(dh + i * 8)     = h0;
                *(uint32_t*)(dh + i * 8 + 4) = h1;
                *(uint32_t*)(dl + i * 8)     = l0;
                *(uint32_t*)(dl + i * 8 + 4) = l1;
            }
        }
        // stage W0 chunk (2 x 33280 B = 2 x 2080 uint4)
        {
            const uint4* sh = (const uint4*)g_W0img[0][t][c];
            const uint4* sl = (const uint4*)g_W0img[1][t][c];
            uint4* dh = (uint4*)(smem + W0H_OFF);
            uint4* dl = (uint4*)(smem + W0L_OFF);
            for (int i = tid; i < 2080; i += 256) { dh[i] = sh[i]; dl[i] = sl[i]; }
        }
        __syncthreads();

        #pragma unroll
        for (int ks = 0; ks < 6; ks++) {
            const uint32_t kb = ks * 32;
            uint32_t Ah[2][4], Al[2][4];
            ldm_x4(Ah[0], aH0 + kb);
            ldm_x4(Ah[1], aH0 + 16 * 208 + kb);
            ldm_x4(Al[0], aL0 + kb);
            ldm_x4(Al[1], aL0 + 16 * 208 + kb);
            #pragma unroll
            for (int g = 0; g < 5; g++) {
                uint32_t Bh[4], Bl[4];
                ldm_x4(Bh, bH0 + g * (16 * 208) + kb);
                ldm_x4(Bl, bL0 + g * (16 * 208) + kb);
                #pragma unroll
                for (int s = 0; s < 2; s++) {
                    int nt = g * 2 + s;
                    #pragma unroll
                    for (int mt = 0; mt < 2; mt++) {
                        mma_bf16(acc0[mt][nt], Ah[mt], Bh + s * 2);
                        mma_bf16(acc0[mt][nt], Al[mt], Bh + s * 2);
                        mma_bf16(acc0[mt][nt], Ah[mt], Bl + s * 2);
                    }
                }
            }
        }
    }
    __syncthreads();  // all L0 reads done before H0 region reused? (H0 distinct; this orders epilogue writes)

    // epilogue 0 -> H0 (stride 336), celu + split
    #pragma unroll
    for (int mt = 0; mt < 2; mt++) {
        int row0 = mb + mt * 16 + (lane >> 2);
        #pragma unroll
        for (int nt = 0; nt < 10; nt++) {
            int col = nw * 80 + nt * 8 + 2 * (lane & 3);
            float* d = acc0[mt][nt];
            float v0 = celu_f(d[0] + sBias[col]);
            float v1 = celu_f(d[1] + sBias[col + 1]);
            float v2 = celu_f(d[2] + sBias[col]);
            float v3 = celu_f(d[3] + sBias[col + 1]);
            uint32_t h, l;
            split2(v0, v1, h, l);
            *(uint32_t*)(smem + H0H_OFF + row0 * 336 + col * 2) = h;
            *(uint32_t*)(smem + H0L_OFF + row0 * 336 + col * 2) = l;
            split2(v2, v3, h, l);
            *(uint32_t*)(smem + H0H_OFF + (row0 + 8) * 336 + col * 2) = h;
            *(uint32_t*)(smem + H0L_OFF + (row0 + 8) * 336 + col * 2) = l;
        }
    }
    __syncthreads();

    // ===================== LAYER 1: 160 -> 128 (two 64-N halves) =====================
    const uint32_t aH1 = sb + H0H_OFF + (mb + arow) * 336 + akb;
    const uint32_t aL1 = sb + H0L_OFF + (mb + arow) * 336 + akb;
    const uint32_t bH1 = sb + W1H_OFF + (nw * 32 + brow) * 336 + bkb;
    const uint32_t bL1 = sb + W1L_OFF + (nw * 32 + brow) * 336 + bkb;

    for (int half = 0; half < 2; half++) {
        if (half) __syncthreads();
        {
            const uint4* sh = (const uint4*)g_W1img[0][t][half];
            const uint4* sl = (const uint4*)g_W1img[1][t][half];
            uint4* dh = (uint4*)(smem + W1H_OFF);
            uint4* dl = (uint4*)(smem + W1L_OFF);
            for (int i = tid; i < 1344; i += 256) { dh[i] = sh[i]; dl[i] = sl[i]; }
        }
        __syncthreads();

        float acc1[2][4][4];
        #pragma unroll
        for (int mt = 0; mt < 2; mt++)
            #pragma unroll
            for (int nt = 0; nt < 4; nt++)
                #pragma unroll
                for (int q = 0; q < 4; q++) acc1[mt][nt][q] = 0.f;

        #pragma unroll
        for (int ks = 0; ks < 10; ks++) {
            const uint32_t kb = ks * 32;
            uint32_t Ah[2][4], Al[2][4];
            ldm_x4(Ah[0], aH1 + kb);
            ldm_x4(Ah[1], aH1 + 16 * 336 + kb);
            ldm_x4(Al[0], aL1 + kb);
            ldm_x4(Al[1], aL1 + 16 * 336 + kb);
            #pragma unroll
            for (int g = 0; g < 2; g++) {
                uint32_t Bh[4], Bl[4];
                ldm_x4(Bh, bH1 + g * (16 * 336) + kb);
                ldm_x4(Bl, bL1 + g * (16 * 336) + kb);
                #pragma unroll
                for (int s = 0; s < 2; s++) {
                    int nt = g * 2 + s;
                    #pragma unroll
                    for (int mt = 0; mt < 2; mt++) {
                        mma_bf16(acc1[mt][nt], Ah[mt], Bh + s * 2);
                        mma_bf16(acc1[mt][nt], Al[mt], Bh + s * 2);
                        mma_bf16(acc1[mt][nt], Ah[mt], Bl + s * 2);
                    }
                }
            }
        }

        // epilogue 1 -> H1 (stride 272)
        #pragma unroll
        for (int mt = 0; mt < 2; mt++) {
            int row0 = mb + mt * 16 + (lane >> 2);
            #pragma unroll
            for (int nt = 0; nt < 4; nt++) {
                int col = half * 64 + nw * 32 + nt * 8 + 2 * (lane & 3);
                float* d = acc1[mt][nt];
                float v0 = celu_f(d[0] + sBias[160 + col]);
                float v1 = celu_f(d[1] + sBias[160 + col + 1]);
                float v2 = celu_f(d[2] + sBias[160 + col]);
                float v3 = celu_f(d[3] + sBias[160 + col + 1]);
                uint32_t h, l;
                split2(v0, v1, h, l);
                *(uint32_t*)(smem + H1H_OFF + row0 * 272 + col * 2) = h;
                *(uint32_t*)(smem + H1L_OFF + row0 * 272 + col * 2) = l;
                split2(v2, v3, h, l);
                *(uint32_t*)(smem + H1H_OFF + (row0 + 8) * 272 + col * 2) = h;
                *(uint32_t*)(smem + H1L_OFF + (row0 + 8) * 272 + col * 2) = l;
            }
        }
    }
    __syncthreads();

    // ===================== LAYER 2: 128 -> 96 (+ fused layer 3) =====================
    {
        const uint4* sh = (const uint4*)g_W2img[0][t];
        const uint4* sl = (const uint4*)g_W2img[1][t];
        uint4* dh = (uint4*)(smem + W2H_OFF);
        uint4* dl = (uint4*)(smem + W2L_OFF);
        for (int i = tid; i < 1632; i += 256) { dh[i] = sh[i]; dl[i] = sl[i]; }
    }
    __syncthreads();

    float acc2[2][6][4];
    #pragma unroll
    for (int mt = 0; mt < 2; mt++)
        #pragma unroll
        for (int nt = 0; nt < 6; nt++)
            #pragma unroll
            for (int q = 0; q < 4; q++) acc2[mt][nt][q] = 0.f;

    const uint32_t aH2 = sb + H1H_OFF + (mb + arow) * 272 + akb;
    const uint32_t aL2 = sb + H1L_OFF + (mb + arow) * 272 + akb;
    const uint32_t bH2 = sb + W2H_OFF + (nw * 48 + brow) * 272 + bkb;
    const uint32_t bL2 = sb + W2L_OFF + (nw * 48 + brow) * 272 + bkb;

    #pragma unroll
    for (int ks = 0; ks < 8; ks++) {
        const uint32_t kb = ks * 32;
        uint32_t Ah[2][4], Al[2][4];
        ldm_x4(Ah[0], aH2 + kb);
        ldm_x4(Ah[1], aH2 + 16 * 272 + kb);
        ldm_x4(Al[0], aL2 + kb);
        ldm_x4(Al[1], aL2 + 16 * 272 + kb);
        #pragma unroll
        for (int g = 0; g < 3; g++) {
            uint32_t Bh[4], Bl[4];
            ldm_x4(Bh, bH2 + g * (16 * 272) + kb);
            ldm_x4(Bl, bL2 + g * (16 * 272) + kb);
            #pragma unroll
            for (int s = 0; s < 2; s++) {
                int nt = g * 2 + s;
                #pragma unroll
                for (int mt = 0; mt < 2; mt++) {
                    mma_bf16(acc2[mt][nt], Ah[mt], Bh + s * 2);
                    mma_bf16(acc2[mt][nt], Al[mt], Bh + s * 2);
                    mma_bf16(acc2[mt][nt], Ah[mt], Bl + s * 2);
                }
            }
        }
    }

    // layer-3 fused epilogue: e[row] = b3 + sum_col celu(x+b2[col]) * w3[col]
    {
        float part[2][2] = {{0.f, 0.f}, {0.f, 0.f}};
        #pragma unroll
        for (int mt = 0; mt < 2; mt++)
            #pragma unroll
            for (int nt = 0; nt < 6; nt++) {
                int col = nw * 48 + nt * 8 + 2 * (lane & 3);
                float* d = acc2[mt][nt];
                part[mt][0] += celu_f(d[0] + sBias[288 + col]) * sBias[384 + col]
                             + celu_f(d[1] + sBias[288 + col + 1]) * sBias[384 + col + 1];
                part[mt][1] += celu_f(d[2] + sBias[288 + col]) * sBias[384 + col]
                             + celu_f(d[3] + sBias[288 + col + 1]) * sBias[384 + col + 1];
            }
        #pragma unroll
        for (int mt = 0; mt < 2; mt++)
            #pragma unroll
            for (int h = 0; h < 2; h++) {
                part[mt][h] += __shfl_xor_sync(0xffffffffu, part[mt][h], 1);
                part[mt][h] += __shfl_xor_sync(0xffffffffu, part[mt][h], 2);
            }
        if ((lane & 3) == 0) {
            #pragma unroll
            for (int mt = 0; mt < 2; mt++)
                #pragma unroll
                for (int h = 0; h < 2; h++) {
                    int row = mb + mt * 16 + h * 8 + (lane >> 2);
                    atomicAdd(&sE[row], part[mt][h]);
                }
        }
    }
    __syncthreads();
    if (tid < 128) {
        int gi = sIdx[tid];
        if (gi >= 0) g_atom_e[gi] = sE[tid] + sBias[480];
    }
}

// ---------------- output assembly ----------------
__global__ void k_finalize(const int* __restrict__ sp,
                           float* __restrict__ out_head,
                           float* __restrict__ out_e)
{
    int b  = blockIdx.x;
    int tx = threadIdx.x;
    int i  = b * NA + tx;
    float e = g_atom_e[i];
    if (out_head) out_head[i] = (float)get_sp(sp, i, g_is64);
    #pragma unroll
    for (int o = 16; o > 0; o >>= 1) e += __shfl_down_sync(0xffffffffu, e, o);
    __shared__ float s2[2];
    if ((tx & 31) == 0) s2[tx >> 5] = e;
    __syncthreads();
    if (tx == 0) out_e[b] = s2[0] + s2[1];
}

extern "C" void kernel_launch(void* const* d_in, const int* in_sizes, int n_in,
                              void* d_out, int out_size)
{
    const int*   sp  = (const int*)d_in[0];
    const float* aev = (const float*)d_in[1];
    const float* W0 = (const float*)d_in[2];
    const float* b0 = (const float*)d_in[3];
    const float* W1 = (const float*)d_in[4];
    const float* b1 = (const float*)d_in[5];
    const float* W2 = (const float*)d_in[6];
    const float* b2 = (const float*)d_in[7];
    const float* W3 = (const float*)d_in[8];
    const float* b3 = (const float*)d_in[9];

    float* out = (float*)d_out;
    float* out_head;
    float* out_e;
    if (out_size == NB) { out_head = nullptr; out_e = out; }
    else                { out_head = out;     out_e = out + (out_size - NB); }

    k_detect <<<1, 32>>>(sp);
    k_count  <<<NATOMS / 256, 256>>>(sp);
    k_build  <<<1, 1>>>();
    k_scatter<<<NATOMS / 256, 256>>>(sp);
    k_prep   <<<(PREP_TOTAL + 255) / 256, 256>>>(W0, W1, W2);

    cudaFuncSetAttribute(k_mlp_tc, cudaFuncAttributeMaxDynamicSharedMemorySize, SM_TOTAL);
    k_mlp_tc<<<MAXTILES, 256, SM_TOTAL>>>(aev, b0, b1, b2, W3, b3);

    k_finalize<<<NB, NA>>>(sp, out_head, out_e);
}

// round 5
// speedup vs baseline: 2.6695x; 1.2528x over previous
#include <cuda_runtime.h>
#include <cuda_fp16.h>
#include <cstdint>

// ---------------- problem constants ----------------
#define NB      2048
#define NA      64
#define NATOMS  (NB*NA)
#define AEV     384
#define N0      160
#define N1      128
#define N2      96
#define NTYPES  4
#define TILE    128
#define MAXTILES 1040

// ---------------- device scratch ----------------
__device__ int   g_is64;
__device__ int   g_counts[NTYPES];
__device__ int   g_cursor[NTYPES];
__device__ int   g_offsets[NTYPES];
__device__ int   g_ntiles;
__device__ int   g_tile_type[MAXTILES];
__device__ int   g_tile_start[MAXTILES];
__device__ int   g_tile_len[MAXTILES];
__device__ int   g_perm[NATOMS];
__device__ float g_atom_e[NATOMS];

// fp16 weight images, [n][k] layout, padded strides (bytes): W0 208, W1 336, W2 272
__device__ uint4 g_W0img[NTYPES][4][2080];   // per 96-K chunk: 160*208 B
__device__ uint4 g_W1img[NTYPES][2][1344];   // per 64-N half:  64*336 B (K=160)
__device__ uint4 g_W2img[NTYPES][1632];      // 96*272 B (K=128)

__device__ __forceinline__ float celu_f(float x) {
    return x > 0.f ? x : 0.1f * expm1f(10.f * x);
}
__device__ __forceinline__ int get_sp(const int* __restrict__ raw, int i, int is64) {
    return is64 ? raw[2 * i] : raw[i];
}
__device__ __forceinline__ uint32_t pack2h(float a, float b) {
    __half ha = __float2half_rn(a), hb = __float2half_rn(b);
    return (uint32_t)__half_as_ushort(ha) | ((uint32_t)__half_as_ushort(hb) << 16);
}
__device__ __forceinline__ void split2h(float a, float b, uint32_t& hi, uint32_t& lo) {
    __half ha = __float2half_rn(a), hb = __float2half_rn(b);
    float ra = a - __half2float(ha), rb = b - __half2float(hb);
    hi = (uint32_t)__half_as_ushort(ha) | ((uint32_t)__half_as_ushort(hb) << 16);
    lo = pack2h(ra, rb);
}
__device__ __forceinline__ uint32_t smem_u32(const void* p) {
    uint32_t a;
    asm("{ .reg .u64 t; cvta.to.shared.u64 t, %1; cvt.u32.u64 %0, t; }" : "=r"(a) : "l"(p));
    return a;
}
__device__ __forceinline__ void ldm_x4(uint32_t* r, uint32_t addr) {
    asm volatile("ldmatrix.sync.aligned.m8n8.x4.shared.b16 {%0,%1,%2,%3}, [%4];"
                 : "=r"(r[0]), "=r"(r[1]), "=r"(r[2]), "=r"(r[3]) : "r"(addr));
}
__device__ __forceinline__ void mma_fp16(float* d, const uint32_t* a, const uint32_t* b) {
    asm volatile(
        "mma.sync.aligned.m16n8k16.row.col.f32.f16.f16.f32 "
        "{%0,%1,%2,%3},{%4,%5,%6,%7},{%8,%9},{%0,%1,%2,%3};"
        : "+f"(d[0]), "+f"(d[1]), "+f"(d[2]), "+f"(d[3])
        : "r"(a[0]), "r"(a[1]), "r"(a[2]), "r"(a[3]), "r"(b[0]), "r"(b[1]));
}
__device__ __forceinline__ void cp16(uint32_t s, const void* g) {
    asm volatile("cp.async.cg.shared.global [%0], [%1], 16;" :: "r"(s), "l"(g) : "memory");
}
#define CP_COMMIT() asm volatile("cp.async.commit_group;" ::: "memory")
#define CP_WAIT(n)  asm volatile("cp.async.wait_group %0;" :: "n"(n) : "memory")

// ---------------- sorting pipeline ----------------
__global__ void k_detect(const int* __restrict__ sp_raw) {
    if (threadIdx.x == 0) {
        int odd_nonzero = 0;
        #pragma unroll
        for (int i = 1; i < 64; i += 2) odd_nonzero |= (sp_raw[i] != 0);
        g_is64 = odd_nonzero ? 0 : 1;
    }
    if (threadIdx.x < NTYPES) { g_counts[threadIdx.x] = 0; g_cursor[threadIdx.x] = 0; }
}

__global__ void k_count(const int* __restrict__ sp) {
    __shared__ int c[NTYPES];
    if (threadIdx.x < NTYPES) c[threadIdx.x] = 0;
    __syncthreads();
    int i = blockIdx.x * blockDim.x + threadIdx.x;
    if (i < NATOMS) {
        g_atom_e[i] = 0.f;
        int t = get_sp(sp, i, g_is64);
        if ((unsigned)t < NTYPES) atomicAdd(&c[t], 1);
    }
    __syncthreads();
    if (threadIdx.x < NTYPES && c[threadIdx.x]) atomicAdd(&g_counts[threadIdx.x], c[threadIdx.x]);
}

__global__ void k_build() {
    if (blockIdx.x == 0 && threadIdx.x == 0) {
        int off = 0, nt = 0;
        for (int t = 0; t < NTYPES; t++) {
            g_offsets[t] = off;
            int c = g_counts[t];
            for (int j = 0; j < c && nt < MAXTILES; j += TILE) {
                g_tile_type[nt]  = t;
                g_tile_start[nt] = off + j;
                g_tile_len[nt]   = (c - j) < TILE ? (c - j) : TILE;
                nt++;
            }
            off += c;
        }
        g_ntiles = nt;
    }
}

__global__ void k_scatter(const int* __restrict__ sp) {
    __shared__ int base[NTYPES];
    __shared__ int lc[NTYPES];
    if (threadIdx.x < NTYPES) lc[threadIdx.x] = 0;
    __syncthreads();
    int i = blockIdx.x * blockDim.x + threadIdx.x;
    int t = -1, r = 0;
    if (i < NATOMS) {
        t = get_sp(sp, i, g_is64);
        if ((unsigned)t < NTYPES) r = atomicAdd(&lc[t], 1); else t = -1;
    }
    __syncthreads();
    if (threadIdx.x < NTYPES)
        base[threadIdx.x] = lc[threadIdx.x] ? atomicAdd(&g_cursor[threadIdx.x], lc[threadIdx.x]) : 0;
    __syncthreads();
    if (t >= 0) g_perm[g_offsets[t] + base[t] + r] = i;
}

// ---------------- weight prep (fp32 -> fp16 images) ----------------
#define PREP_W0 122880   // 4t * 4c * 160n * 48j
#define PREP_W1 40960    // 4t * 2h * 64n * 80j
#define PREP_W2 24576    // 4t * 96n * 64j
#define PREP_TOTAL (PREP_W0 + PREP_W1 + PREP_W2)

__global__ void k_prep(const float* __restrict__ W0, const float* __restrict__ W1,
                       const float* __restrict__ W2) {
    int idx = blockIdx.x * blockDim.x + threadIdx.x;
    if (idx < PREP_W0) {
        int t = idx / 30720, r = idx % 30720;
        int c = r / 7680;  r %= 7680;
        int n = r / 48, j = r % 48;
        int k0 = c * 96 + 2 * j;
        float v0 = W0[((size_t)t * AEV + k0)     * N0 + n];
        float v1 = W0[((size_t)t * AEV + k0 + 1) * N0 + n];
        *(uint32_t*)((char*)g_W0img[t][c] + n * 208 + j * 4) = pack2h(v0, v1);
    } else if (idx < PREP_W0 + PREP_W1) {
        int i2 = idx - PREP_W0;
        int t = i2 / 10240, r = i2 % 10240;
        int h = r / 5120;  r %= 5120;
        int n = r / 80, j = r % 80;
        int k0 = 2 * j;
        float v0 = W1[((size_t)t * N0 + k0)     * N1 + h * 64 + n];
        float v1 = W1[((size_t)t * N0 + k0 + 1) * N1 + h * 64 + n];
        *(uint32_t*)((char*)g_W1img[t][h] + n * 336 + j * 4) = pack2h(v0, v1);
    } else if (idx < PREP_TOTAL) {
        int i3 = idx - PREP_W0 - PREP_W1;
        int t = i3 / 6144, r = i3 % 6144;
        int n = r / 64, j = r % 64;
        int k0 = 2 * j;
        float v0 = W2[((size_t)t * N1 + k0)     * N2 + n];
        float v1 = W2[((size_t)t * N1 + k0 + 1) * N2 + n];
        *(uint32_t*)((char*)g_W2img[t] + n * 272 + j * 4) = pack2h(v0, v1);
    }
}

// ---------------- fused MLP (mma.sync fp16, A split h/l, W single fp16) ----------------
// SMEM arena (bytes):
#define XH_OFF  0            // 128*208 = 26624
#define XL_OFF  26624        // ..53248
#define W0_OFF  53248        // 2 bufs * 33280 -> ..119808
#define H0H_OFF 119808       // 128*336 = 43008 -> ..162816
#define H0L_OFF 162816       // ..205824
#define W1_OFF  0            // 2 halves * 21504 -> ..43008 (over X, after L0)
#define H1H_OFF 43008        // 128*272 = 34816 -> ..77824  (over W0, after L0)
#define H1L_OFF 77824        // ..112640
#define W2_OFF  119808       // 26112 -> ..145920 (over H0H, after L1)
#define SIDX_OFF 205824
#define SE_OFF   206336
#define BIAS_OFF 206848      // 482 floats
#define SM_TOTAL 208896

__global__ __launch_bounds__(256, 1)
void k_mlp_tc(const float* __restrict__ aev,
              const float* __restrict__ b0, const float* __restrict__ b1,
              const float* __restrict__ b2, const float* __restrict__ W3,
              const float* __restrict__ b3)
{
    int bt = blockIdx.x;
    if (bt >= g_ntiles) return;

    extern __shared__ char smem[];
    const uint32_t sb = smem_u32(smem);
    int*   sIdx  = (int*)(smem + SIDX_OFF);
    float* sE    = (float*)(smem + SE_OFF);
    float* sBias = (float*)(smem + BIAS_OFF);

    const int tid  = threadIdx.x;
    const int lane = tid & 31;
    const int w    = tid >> 5;
    const int mb   = (w & 3) * 32;   // warp M base
    const int nw   = (w >> 2);       // warp N group (0/1)

    const int t      = g_tile_type[bt];
    const int gstart = g_tile_start[bt];
    const int len    = g_tile_len[bt];

    if (tid < 128) {
        sIdx[tid] = (tid < len) ? g_perm[gstart + tid] : -1;
        sE[tid] = 0.f;
    }
    for (int i = tid; i < N0; i += 256) sBias[i] = b0[t * N0 + i];
    for (int i = tid; i < N1; i += 256) sBias[160 + i] = b1[t * N1 + i];
    for (int i = tid; i < N2; i += 256) { sBias[288 + i] = b2[t * N2 + i]; sBias[384 + i] = W3[t * N2 + i]; }
    if (tid == 0) sBias[480] = b3[t];

    // prefetch W0 chunk 0 into buf 0
    {
        const uint4* src = g_W0img[t][0];
        uint32_t dst = sb + W0_OFF;
        for (int i = tid; i < 2080; i += 256) cp16(dst + i * 16, src + i);
        CP_COMMIT();
    }
    __syncthreads();

    // lane offsets for ldmatrix
    const int arow = (lane & 7) + (lane & 8);
    const int akb  = (lane & 16) ? 16 : 0;
    const int brow = (lane & 7) + ((lane & 16) ? 8 : 0);
    const int bkb  = (lane & 8) ? 16 : 0;

    // ===================== LAYER 0: 384 -> 160 =====================
    float acc0[2][10][4];
    #pragma unroll
    for (int mt = 0; mt < 2; mt++)
        #pragma unroll
        for (int nt = 0; nt < 10; nt++)
            #pragma unroll
            for (int q = 0; q < 4; q++) acc0[mt][nt][q] = 0.f;

    const uint32_t aH0 = sb + XH_OFF + (mb + arow) * 208 + akb;
    const uint32_t aL0 = sb + XL_OFF + (mb + arow) * 208 + akb;

    for (int c = 0; c < 4; c++) {
        int buf = c & 1;
        if (c) __syncthreads();                     // prior chunk MMA reads done
        if (c < 3) {                                // prefetch next W0 chunk
            const uint4* src = g_W0img[t][c + 1];
            uint32_t dst = sb + W0_OFF + (buf ^ 1) * 33280;
            for (int i = tid; i < 2080; i += 256) cp16(dst + i * 16, src + i);
            CP_COMMIT();
        }
        // stage X chunk: row = tid/2, 48 cols per half-thread, split fp16 h/l
        {
            int row  = tid >> 1;
            int col0 = (tid & 1) * 48;
            int gi   = sIdx[row];
            const float4* src = (const float4*)(aev + (size_t)(gi < 0 ? 0 : gi) * AEV + c * 96 + col0);
            char* dh = smem + XH_OFF + row * 208 + col0 * 2;
            char* dl = smem + XL_OFF + row * 208 + col0 * 2;
            #pragma unroll
            for (int i = 0; i < 12; i++) {
                float4 v = (gi >= 0) ? src[i] : make_float4(0.f, 0.f, 0.f, 0.f);
                uint32_t h0, l0, h1, l1;
                split2h(v.x, v.y, h0, l0);
                split2h(v.z, v.w, h1, l1);
                *(uint32_t*)(dh + i * 8)     = h0;
                *(uint32_t*)(dh + i * 8 + 4) = h1;
                *(uint32_t*)(dl + i * 8)     = l0;
                *(uint32_t*)(dl + i * 8 + 4) = l1;
            }
        }
        if (c < 3) { CP_WAIT(1); } else { CP_WAIT(0); }
        __syncthreads();

        const uint32_t bB = sb + W0_OFF + buf * 33280 + (nw * 80 + brow) * 208 + bkb;
        #pragma unroll
        for (int ks = 0; ks < 6; ks++) {
            const uint32_t kb = ks * 32;
            uint32_t Ah[2][4], Al[2][4];
            ldm_x4(Ah[0], aH0 + kb);
            ldm_x4(Ah[1], aH0 + 16 * 208 + kb);
            ldm_x4(Al[0], aL0 + kb);
            ldm_x4(Al[1], aL0 + 16 * 208 + kb);
            #pragma unroll
            for (int g = 0; g < 5; g++) {
                uint32_t Bh[4];
                ldm_x4(Bh, bB + g * (16 * 208) + kb);
                #pragma unroll
                for (int s = 0; s < 2; s++) {
                    int nt = g * 2 + s;
                    #pragma unroll
                    for (int mt = 0; mt < 2; mt++) {
                        mma_fp16(acc0[mt][nt], Ah[mt], Bh + s * 2);
                        mma_fp16(acc0[mt][nt], Al[mt], Bh + s * 2);
                    }
                }
            }
        }
    }
    __syncthreads();   // all L0 MMA reads of X/W0 done -> X/W0 regions reusable

    // prefetch W1 halves into W1_OFF (over dead X region)
    {
        const uint4* s0 = g_W1img[t][0];
        const uint4* s1 = g_W1img[t][1];
        uint32_t d0 = sb + W1_OFF;
        uint32_t d1 = sb + W1_OFF + 21504;
        for (int i = tid; i < 1344; i += 256) { cp16(d0 + i * 16, s0 + i); cp16(d1 + i * 16, s1 + i); }
        CP_COMMIT();
    }

    // epilogue 0 -> H0 (stride 336), celu + fp16 split
    #pragma unroll
    for (int mt = 0; mt < 2; mt++) {
        int row0 = mb + mt * 16 + (lane >> 2);
        #pragma unroll
        for (int nt = 0; nt < 10; nt++) {
            int col = nw * 80 + nt * 8 + 2 * (lane & 3);
            float* d = acc0[mt][nt];
            float v0 = celu_f(d[0] + sBias[col]);
            float v1 = celu_f(d[1] + sBias[col + 1]);
            float v2 = celu_f(d[2] + sBias[col]);
            float v3 = celu_f(d[3] + sBias[col + 1]);
            uint32_t h, l;
            split2h(v0, v1, h, l);
            *(uint32_t*)(smem + H0H_OFF + row0 * 336 + col * 2) = h;
            *(uint32_t*)(smem + H0L_OFF + row0 * 336 + col * 2) = l;
            split2h(v2, v3, h, l);
            *(uint32_t*)(smem + H0H_OFF + (row0 + 8) * 336 + col * 2) = h;
            *(uint32_t*)(smem + H0L_OFF + (row0 + 8) * 336 + col * 2) = l;
        }
    }
    CP_WAIT(0);
    __syncthreads();

    // ===================== LAYER 1: 160 -> 128 (two 64-N halves) =====================
    const uint32_t aH1 = sb + H0H_OFF + (mb + arow) * 336 + akb;
    const uint32_t aL1 = sb + H0L_OFF + (mb + arow) * 336 + akb;

    for (int half = 0; half < 2; half++) {
        float acc1[2][4][4];
        #pragma unroll
        for (int mt = 0; mt < 2; mt++)
            #pragma unroll
            for (int nt = 0; nt < 4; nt++)
                #pragma unroll
                for (int q = 0; q < 4; q++) acc1[mt][nt][q] = 0.f;

        const uint32_t bB = sb + W1_OFF + half * 21504 + (nw * 32 + brow) * 336 + bkb;
        #pragma unroll
        for (int ks = 0; ks < 10; ks++) {
            const uint32_t kb = ks * 32;
            uint32_t Ah[2][4], Al[2][4];
            ldm_x4(Ah[0], aH1 + kb);
            ldm_x4(Ah[1], aH1 + 16 * 336 + kb);
            ldm_x4(Al[0], aL1 + kb);
            ldm_x4(Al[1], aL1 + 16 * 336 + kb);
            #pragma unroll
            for (int g = 0; g < 2; g++) {
                uint32_t Bh[4];
                ldm_x4(Bh, bB + g * (16 * 336) + kb);
                #pragma unroll
                for (int s = 0; s < 2; s++) {
                    int nt = g * 2 + s;
                    #pragma unroll
                    for (int mt = 0; mt < 2; mt++) {
                        mma_fp16(acc1[mt][nt], Ah[mt], Bh + s * 2);
                        mma_fp16(acc1[mt][nt], Al[mt], Bh + s * 2);
                    }
                }
            }
        }

        // epilogue 1 -> H1 (stride 272); region disjoint from H0/W1, no sync needed
        #pragma unroll
        for (int mt = 0; mt < 2; mt++) {
            int row0 = mb + mt * 16 + (lane >> 2);
            #pragma unroll
            for (int nt = 0; nt < 4; nt++) {
                int col = half * 64 + nw * 32 + nt * 8 + 2 * (lane & 3);
                float* d = acc1[mt][nt];
                float v0 = celu_f(d[0] + sBias[160 + col]);
                float v1 = celu_f(d[1] + sBias[160 + col + 1]);
                float v2 = celu_f(d[2] + sBias[160 + col]);
                float v3 = celu_f(d[3] + sBias[160 + col + 1]);
                uint32_t h, l;
                split2h(v0, v1, h, l);
                *(uint32_t*)(smem + H1H_OFF + row0 * 272 + col * 2) = h;
                *(uint32_t*)(smem + H1L_OFF + row0 * 272 + col * 2) = l;
                split2h(v2, v3, h, l);
                *(uint32_t*)(smem + H1H_OFF + (row0 + 8) * 272 + col * 2) = h;
                *(uint32_t*)(smem + H1L_OFF + (row0 + 8) * 272 + col * 2) = l;
            }
        }
    }
    __syncthreads();   // all warps done reading H0 -> H0H region reusable for W2

    // stage W2 (over dead H0H region)
    {
        const uint4* src = g_W2img[t];
        uint32_t dst = sb + W2_OFF;
        for (int i = tid; i < 1632; i += 256) cp16(dst + i * 16, src + i);
        CP_COMMIT();
        CP_WAIT(0);
    }
    __syncthreads();

    // ===================== LAYER 2: 128 -> 96 (+ fused layer 3) =====================
    float acc2[2][6][4];
    #pragma unroll
    for (int mt = 0; mt < 2; mt++)
        #pragma unroll
        for (int nt = 0; nt < 6; nt++)
            #pragma unroll
            for (int q = 0; q < 4; q++) acc2[mt][nt][q] = 0.f;

    const uint32_t aH2 = sb + H1H_OFF + (mb + arow) * 272 + akb;
    const uint32_t aL2 = sb + H1L_OFF + (mb + arow) * 272 + akb;
    const uint32_t bB2 = sb + W2_OFF + (nw * 48 + brow) * 272 + bkb;

    #pragma unroll
    for (int ks = 0; ks < 8; ks++) {
        const uint32_t kb = ks * 32;
        uint32_t Ah[2][4], Al[2][4];
        ldm_x4(Ah[0], aH2 + kb);
        ldm_x4(Ah[1], aH2 + 16 * 272 + kb);
        ldm_x4(Al[0], aL2 + kb);
        ldm_x4(Al[1], aL2 + 16 * 272 + kb);
        #pragma unroll
        for (int g = 0; g < 3; g++) {
            uint32_t Bh[4];
            ldm_x4(Bh, bB2 + g * (16 * 272) + kb);
            #pragma unroll
            for (int s = 0; s < 2; s++) {
                int nt = g * 2 + s;
                #pragma unroll
                for (int mt = 0; mt < 2; mt++) {
                    mma_fp16(acc2[mt][nt], Ah[mt], Bh + s * 2);
                    mma_fp16(acc2[mt][nt], Al[mt], Bh + s * 2);
                }
            }
        }
    }

    // layer-3 fused epilogue: e[row] = b3 + sum_col celu(x+b2[col]) * w3[col]
    {
        float part[2][2] = {{0.f, 0.f}, {0.f, 0.f}};
        #pragma unroll
        for (int mt = 0; mt < 2; mt++)
            #pragma unroll
            for (int nt = 0; nt < 6; nt++) {
                int col = nw * 48 + nt * 8 + 2 * (lane & 3);
                float* d = acc2[mt][nt];
                part[mt][0] += celu_f(d[0] + sBias[288 + col]) * sBias[384 + col]
                             + celu_f(d[1] + sBias[288 + col + 1]) * sBias[384 + col + 1];
                part[mt][1] += celu_f(d[2] + sBias[288 + col]) * sBias[384 + col]
                             + celu_f(d[3] + sBias[288 + col + 1]) * sBias[384 + col + 1];
            }
        #pragma unroll
        for (int mt = 0; mt < 2; mt++)
            #pragma unroll
            for (int h = 0; h < 2; h++) {
                part[mt][h] += __shfl_xor_sync(0xffffffffu, part[mt][h], 1);
                part[mt][h] += __shfl_xor_sync(0xffffffffu, part[mt][h], 2);
            }
        if ((lane & 3) == 0) {
            #pragma unroll
            for (int mt = 0; mt < 2; mt++)
                #pragma unroll
                for (int h = 0; h < 2; h++) {
                    int row = mb + mt * 16 + h * 8 + (lane >> 2);
                    atomicAdd(&sE[row], part[mt][h]);
                }
        }
    }
    __syncthreads();
    if (tid < 128) {
        int gi = sIdx[tid];
        if (gi >= 0) g_atom_e[gi] = sE[tid] + sBias[480];
    }
}

// ---------------- output assembly ----------------
__global__ void k_finalize(const int* __restrict__ sp,
                           float* __restrict__ out_head,
                           float* __restrict__ out_e)
{
    int b  = blockIdx.x;
    int tx = threadIdx.x;
    int i  = b * NA + tx;
    float e = g_atom_e[i];
    if (out_head) out_head[i] = (float)get_sp(sp, i, g_is64);
    #pragma unroll
    for (int o = 16; o > 0; o >>= 1) e += __shfl_down_sync(0xffffffffu, e, o);
    __shared__ float s2[2];
    if ((tx & 31) == 0) s2[tx >> 5] = e;
    __syncthreads();
    if (tx == 0) out_e[b] = s2[0] + s2[1];
}

extern "C" void kernel_launch(void* const* d_in, const int* in_sizes, int n_in,
                              void* d_out, int out_size)
{
    const int*   sp  = (const int*)d_in[0];
    const float* aev = (const float*)d_in[1];
    const float* W0 = (const float*)d_in[2];
    const float* b0 = (const float*)d_in[3];
    const float* W1 = (const float*)d_in[4];
    const float* b1 = (const float*)d_in[5];
    const float* W2 = (const float*)d_in[6];
    const float* b2 = (const float*)d_in[7];
    const float* W3 = (const float*)d_in[8];
    const float* b3 = (const float*)d_in[9];

    float* out = (float*)d_out;
    float* out_head;
    float* out_e;
    if (out_size == NB) { out_head = nullptr; out_e = out; }
    else                { out_head = out;     out_e = out + (out_size - NB); }

    k_detect <<<1, 32>>>(sp);
    k_count  <<<NATOMS / 256, 256>>>(sp);
    k_build  <<<1, 1>>>();
    k_scatter<<<NATOMS / 256, 256>>>(sp);
    k_prep   <<<(PREP_TOTAL + 255) / 256, 256>>>(W0, W1, W2);

    cudaFuncSetAttribute(k_mlp_tc, cudaFuncAttributeMaxDynamicSharedMemorySize, SM_TOTAL);
    k_mlp_tc<<<MAXTILES, 256, SM_TOTAL>>>(aev, b0, b1, b2, W3, b3);

    k_finalize<<<NB, NA>>>(sp, out_head, out_e);
}

// round 6
// speedup vs baseline: 4.5526x; 1.7054x over previous
#include <cuda_runtime.h>
#include <cuda_fp16.h>
#include <cstdint>

// ---------------- problem constants ----------------
#define NB      2048
#define NA      64
#define NATOMS  (NB*NA)
#define AEV     384
#define N0      160
#define N1      128
#define N2      96
#define NTYPES  4
#define TILE    128
#define MAXTILES 1040

// ---------------- device scratch ----------------
__device__ int   g_is64;
__device__ int   g_counts[NTYPES];
__device__ int   g_cursor[NTYPES];
__device__ int   g_offsets[NTYPES];
__device__ int   g_ntiles;
__device__ int   g_tile_type[MAXTILES];
__device__ int   g_tile_start[MAXTILES];
__device__ int   g_tile_len[MAXTILES];
__device__ int   g_perm[NATOMS];
__device__ float g_atom_e[NATOMS];

// fp16 weight images, [n][k] layout, padded strides (bytes): W0 208, W1 336, W2 272
__device__ uint4 g_W0img[NTYPES][4][2080];   // per 96-K chunk: 160*208 B
__device__ uint4 g_W1img[NTYPES][2][1344];   // per 64-N half:  64*336 B (K=160)
__device__ uint4 g_W2img[NTYPES][1632];      // 96*272 B (K=128)

__device__ __forceinline__ float celu_f(float x) {
    return x > 0.f ? x : 0.1f * expm1f(10.f * x);
}
__device__ __forceinline__ int get_sp(const int* __restrict__ raw, int i, int is64) {
    return is64 ? raw[2 * i] : raw[i];
}
__device__ __forceinline__ uint32_t pack2h(float a, float b) {
    __half ha = __float2half_rn(a), hb = __float2half_rn(b);
    return (uint32_t)__half_as_ushort(ha) | ((uint32_t)__half_as_ushort(hb) << 16);
}
__device__ __forceinline__ uint32_t smem_u32(const void* p) {
    uint32_t a;
    asm("{ .reg .u64 t; cvta.to.shared.u64 t, %1; cvt.u32.u64 %0, t; }" : "=r"(a) : "l"(p));
    return a;
}
__device__ __forceinline__ void ldm_x4(uint32_t* r, uint32_t addr) {
    asm volatile("ldmatrix.sync.aligned.m8n8.x4.shared.b16 {%0,%1,%2,%3}, [%4];"
                 : "=r"(r[0]), "=r"(r[1]), "=r"(r[2]), "=r"(r[3]) : "r"(addr));
}
__device__ __forceinline__ void mma_fp16(float* d, const uint32_t* a, const uint32_t* b) {
    asm volatile(
        "mma.sync.aligned.m16n8k16.row.col.f32.f16.f16.f32 "
        "{%0,%1,%2,%3},{%4,%5,%6,%7},{%8,%9},{%0,%1,%2,%3};"
        : "+f"(d[0]), "+f"(d[1]), "+f"(d[2]), "+f"(d[3])
        : "r"(a[0]), "r"(a[1]), "r"(a[2]), "r"(a[3]), "r"(b[0]), "r"(b[1]));
}
__device__ __forceinline__ void cp16(uint32_t s, const void* g) {
    asm volatile("cp.async.cg.shared.global [%0], [%1], 16;" :: "r"(s), "l"(g) : "memory");
}
#define CP_COMMIT() asm volatile("cp.async.commit_group;" ::: "memory")
#define CP_WAIT(n)  asm volatile("cp.async.wait_group %0;" :: "n"(n) : "memory")

// ---------------- sorting pipeline ----------------
__global__ void k_detect(const int* __restrict__ sp_raw) {
    if (threadIdx.x == 0) {
        int odd_nonzero = 0;
        #pragma unroll
        for (int i = 1; i < 64; i += 2) odd_nonzero |= (sp_raw[i] != 0);
        g_is64 = odd_nonzero ? 0 : 1;
    }
    if (threadIdx.x < NTYPES) { g_counts[threadIdx.x] = 0; g_cursor[threadIdx.x] = 0; }
}

__global__ void k_count(const int* __restrict__ sp) {
    __shared__ int c[NTYPES];
    if (threadIdx.x < NTYPES) c[threadIdx.x] = 0;
    __syncthreads();
    int i = blockIdx.x * blockDim.x + threadIdx.x;
    if (i < NATOMS) {
        g_atom_e[i] = 0.f;
        int t = get_sp(sp, i, g_is64);
        if ((unsigned)t < NTYPES) atomicAdd(&c[t], 1);
    }
    __syncthreads();
    if (threadIdx.x < NTYPES && c[threadIdx.x]) atomicAdd(&g_counts[threadIdx.x], c[threadIdx.x]);
}

__global__ void k_build() {
    if (blockIdx.x == 0 && threadIdx.x == 0) {
        int off = 0, nt = 0;
        for (int t = 0; t < NTYPES; t++) {
            g_offsets[t] = off;
            int c = g_counts[t];
            for (int j = 0; j < c && nt < MAXTILES; j += TILE) {
                g_tile_type[nt]  = t;
                g_tile_start[nt] = off + j;
                g_tile_len[nt]   = (c - j) < TILE ? (c - j) : TILE;
                nt++;
            }
            off += c;
        }
        g_ntiles = nt;
    }
}

__global__ void k_scatter(const int* __restrict__ sp) {
    __shared__ int base[NTYPES];
    __shared__ int lc[NTYPES];
    if (threadIdx.x < NTYPES) lc[threadIdx.x] = 0;
    __syncthreads();
    int i = blockIdx.x * blockDim.x + threadIdx.x;
    int t = -1, r = 0;
    if (i < NATOMS) {
        t = get_sp(sp, i, g_is64);
        if ((unsigned)t < NTYPES) r = atomicAdd(&lc[t], 1); else t = -1;
    }
    __syncthreads();
    if (threadIdx.x < NTYPES)
        base[threadIdx.x] = lc[threadIdx.x] ? atomicAdd(&g_cursor[threadIdx.x], lc[threadIdx.x]) : 0;
    __syncthreads();
    if (t >= 0) g_perm[g_offsets[t] + base[t] + r] = i;
}

// ---------------- weight prep (fp32 -> fp16 images) ----------------
#define PREP_W0 122880   // 4t * 4c * 160n * 48j
#define PREP_W1 40960    // 4t * 2h * 64n * 80j
#define PREP_W2 24576    // 4t * 96n * 64j
#define PREP_TOTAL (PREP_W0 + PREP_W1 + PREP_W2)

__global__ void k_prep(const float* __restrict__ W0, const float* __restrict__ W1,
                       const float* __restrict__ W2) {
    int idx = blockIdx.x * blockDim.x + threadIdx.x;
    if (idx < PREP_W0) {
        int t = idx / 30720, r = idx % 30720;
        int c = r / 7680;  r %= 7680;
        int n = r / 48, j = r % 48;
        int k0 = c * 96 + 2 * j;
        float v0 = W0[((size_t)t * AEV + k0)     * N0 + n];
        float v1 = W0[((size_t)t * AEV + k0 + 1) * N0 + n];
        *(uint32_t*)((char*)g_W0img[t][c] + n * 208 + j * 4) = pack2h(v0, v1);
    } else if (idx < PREP_W0 + PREP_W1) {
        int i2 = idx - PREP_W0;
        int t = i2 / 10240, r = i2 % 10240;
        int h = r / 5120;  r %= 5120;
        int n = r / 80, j = r % 80;
        int k0 = 2 * j;
        float v0 = W1[((size_t)t * N0 + k0)     * N1 + h * 64 + n];
        float v1 = W1[((size_t)t * N0 + k0 + 1) * N1 + h * 64 + n];
        *(uint32_t*)((char*)g_W1img[t][h] + n * 336 + j * 4) = pack2h(v0, v1);
    } else if (idx < PREP_TOTAL) {
        int i3 = idx - PREP_W0 - PREP_W1;
        int t = i3 / 6144, r = i3 % 6144;
        int n = r / 64, j = r % 64;
        int k0 = 2 * j;
        float v0 = W2[((size_t)t * N1 + k0)     * N2 + n];
        float v1 = W2[((size_t)t * N1 + k0 + 1) * N2 + n];
        *(uint32_t*)((char*)g_W2img[t] + n * 272 + j * 4) = pack2h(v0, v1);
    }
}

// ---------------- fused MLP (mma.sync fp16, occupancy 2) ----------------
// SMEM arena (bytes), peak 114176 -> 2 CTAs/SM:
//   BIAS @ 0      : 481 floats (1936)
//   SIDX @ 1936   : 512
//   SE   @ 2448   : 512  (end 2960, pad to 3072)
//   WB   @ 3072   : 33280  (W0 chunk -> W1 half -> W2)
//   X    @ 36352  : 26624  (L0 A; dead after L0)
//   H1   @ 36352  : 34816  (over X; written in L1, read in L2)
//   H0   @ 71168  : 43008  (written L0 epilogue, read L1)
#define BIAS_OFF 0
#define SIDX_OFF 1936
#define SE_OFF   2448
#define WB_OFF   3072
#define X_OFF    36352
#define H1_OFF   36352
#define H0_OFF   71168
#define SM_TOTAL 114176

__global__ __launch_bounds__(256, 2)
void k_mlp_tc(const float* __restrict__ aev,
              const float* __restrict__ b0, const float* __restrict__ b1,
              const float* __restrict__ b2, const float* __restrict__ W3,
              const float* __restrict__ b3)
{
    int bt = blockIdx.x;
    if (bt >= g_ntiles) return;

    extern __shared__ char smem[];
    const uint32_t sb = smem_u32(smem);
    float* sBias = (float*)(smem + BIAS_OFF);
    int*   sIdx  = (int*)(smem + SIDX_OFF);
    float* sE    = (float*)(smem + SE_OFF);

    const int tid  = threadIdx.x;
    const int lane = tid & 31;
    const int w    = tid >> 5;
    const int mb   = (w & 3) * 32;   // warp M base
    const int nw   = (w >> 2);       // warp N group (0/1)

    const int t      = g_tile_type[bt];
    const int gstart = g_tile_start[bt];
    const int len    = g_tile_len[bt];

    if (tid < 128) {
        sIdx[tid] = (tid < len) ? g_perm[gstart + tid] : -1;
        sE[tid] = 0.f;
    }
    for (int i = tid; i < N0; i += 256) sBias[i] = b0[t * N0 + i];
    for (int i = tid; i < N1; i += 256) sBias[160 + i] = b1[t * N1 + i];
    for (int i = tid; i < N2; i += 256) { sBias[288 + i] = b2[t * N2 + i]; sBias[384 + i] = W3[t * N2 + i]; }
    if (tid == 0) sBias[480] = b3[t];

    // prefetch W0 chunk 0
    {
        const uint4* src = g_W0img[t][0];
        for (int i = tid; i < 2080; i += 256) cp16(sb + WB_OFF + i * 16, src + i);
        CP_COMMIT();
    }
    __syncthreads();

    // lane offsets for ldmatrix
    const int arow = (lane & 7) + (lane & 8);
    const int akb  = (lane & 16) ? 16 : 0;
    const int brow = (lane & 7) + ((lane & 16) ? 8 : 0);
    const int bkb  = (lane & 8) ? 16 : 0;

    // ===================== LAYER 0: 384 -> 160 =====================
    float acc0[2][10][4];
    #pragma unroll
    for (int mt = 0; mt < 2; mt++)
        #pragma unroll
        for (int nt = 0; nt < 10; nt++)
            #pragma unroll
            for (int q = 0; q < 4; q++) acc0[mt][nt][q] = 0.f;

    const uint32_t aX = sb + X_OFF + (mb + arow) * 208 + akb;
    const uint32_t bW0 = sb + WB_OFF + (nw * 80 + brow) * 208 + bkb;

    for (int c = 0; c < 4; c++) {
        // stage X chunk c: row = tid/2, 48 cols per half-thread, fp16
        {
            int row  = tid >> 1;
            int col0 = (tid & 1) * 48;
            int gi   = sIdx[row];
            const float4* src = (const float4*)(aev + (size_t)(gi < 0 ? 0 : gi) * AEV + c * 96 + col0);
            char* dx = smem + X_OFF + row * 208 + col0 * 2;
            #pragma unroll
            for (int i = 0; i < 12; i++) {
                float4 v = (gi >= 0) ? src[i] : make_float4(0.f, 0.f, 0.f, 0.f);
                *(uint32_t*)(dx + i * 8)     = pack2h(v.x, v.y);
                *(uint32_t*)(dx + i * 8 + 4) = pack2h(v.z, v.w);
            }
        }
        CP_WAIT(0);
        __syncthreads();          // W0 chunk + X ready

        #pragma unroll
        for (int ks = 0; ks < 6; ks++) {
            const uint32_t kb = ks * 32;
            uint32_t A[2][4];
            ldm_x4(A[0], aX + kb);
            ldm_x4(A[1], aX + 16 * 208 + kb);
            #pragma unroll
            for (int g = 0; g < 5; g++) {
                uint32_t B[4];
                ldm_x4(B, bW0 + g * (16 * 208) + kb);
                #pragma unroll
                for (int s = 0; s < 2; s++) {
                    int nt = g * 2 + s;
                    #pragma unroll
                    for (int mt = 0; mt < 2; mt++)
                        mma_fp16(acc0[mt][nt], A[mt], B + s * 2);
                }
            }
        }
        __syncthreads();          // all reads of X/WB done before overwrite

        if (c < 3) {              // stage next W0 chunk (overlaps next X staging)
            const uint4* src = g_W0img[t][c + 1];
            for (int i = tid; i < 2080; i += 256) cp16(sb + WB_OFF + i * 16, src + i);
            CP_COMMIT();
        }
    }

    // prefetch W1 half 0 into WB (WB free: last L0 MMA reads done)
    {
        const uint4* src = g_W1img[t][0];
        for (int i = tid; i < 1344; i += 256) cp16(sb + WB_OFF + i * 16, src + i);
        CP_COMMIT();
    }

    // epilogue 0 -> H0 (stride 336), celu, fp16
    #pragma unroll
    for (int mt = 0; mt < 2; mt++) {
        int row0 = mb + mt * 16 + (lane >> 2);
        #pragma unroll
        for (int nt = 0; nt < 10; nt++) {
            int col = nw * 80 + nt * 8 + 2 * (lane & 3);
            float* d = acc0[mt][nt];
            float v0 = celu_f(d[0] + sBias[col]);
            float v1 = celu_f(d[1] + sBias[col + 1]);
            float v2 = celu_f(d[2] + sBias[col]);
            float v3 = celu_f(d[3] + sBias[col + 1]);
            *(uint32_t*)(smem + H0_OFF + row0 * 336 + col * 2)       = pack2h(v0, v1);
            *(uint32_t*)(smem + H0_OFF + (row0 + 8) * 336 + col * 2) = pack2h(v2, v3);
        }
    }
    CP_WAIT(0);
    __syncthreads();

    // ===================== LAYER 1: 160 -> 128 (two 64-N halves) =====================
    const uint32_t aH0 = sb + H0_OFF + (mb + arow) * 336 + akb;
    const uint32_t bW1 = sb + WB_OFF + (nw * 32 + brow) * 336 + bkb;

    for (int half = 0; half < 2; half++) {
        float acc1[2][4][4];
        #pragma unroll
        for (int mt = 0; mt < 2; mt++)
            #pragma unroll
            for (int nt = 0; nt < 4; nt++)
                #pragma unroll
                for (int q = 0; q < 4; q++) acc1[mt][nt][q] = 0.f;

        #pragma unroll
        for (int ks = 0; ks < 10; ks++) {
            const uint32_t kb = ks * 32;
            uint32_t A[2][4];
            ldm_x4(A[0], aH0 + kb);
            ldm_x4(A[1], aH0 + 16 * 336 + kb);
            #pragma unroll
            for (int g = 0; g < 2; g++) {
                uint32_t B[4];
                ldm_x4(B, bW1 + g * (16 * 336) + kb);
                #pragma unroll
                for (int s = 0; s < 2; s++) {
                    int nt = g * 2 + s;
                    #pragma unroll
                    for (int mt = 0; mt < 2; mt++)
                        mma_fp16(acc1[mt][nt], A[mt], B + s * 2);
                }
            }
        }

        // epilogue 1 -> H1 cols [half*64, half*64+64) (stride 272); H1 region disjoint from H0/WB
        #pragma unroll
        for (int mt = 0; mt < 2; mt++) {
            int row0 = mb + mt * 16 + (lane >> 2);
            #pragma unroll
            for (int nt = 0; nt < 4; nt++) {
                int col = half * 64 + nw * 32 + nt * 8 + 2 * (lane & 3);
                float* d = acc1[mt][nt];
                float v0 = celu_f(d[0] + sBias[160 + col]);
                float v1 = celu_f(d[1] + sBias[160 + col + 1]);
                float v2 = celu_f(d[2] + sBias[160 + col]);
                float v3 = celu_f(d[3] + sBias[160 + col + 1]);
                *(uint32_t*)(smem + H1_OFF + row0 * 272 + col * 2)       = pack2h(v0, v1);
                *(uint32_t*)(smem + H1_OFF + (row0 + 8) * 272 + col * 2) = pack2h(v2, v3);
            }
        }

        if (half == 0) {   // swap in W1 half 1
            __syncthreads();                      // all warps done reading WB (half 0)
            const uint4* src = g_W1img[t][1];
            for (int i = tid; i < 1344; i += 256) cp16(sb + WB_OFF + i * 16, src + i);
            CP_COMMIT();
            CP_WAIT(0);
            __syncthreads();
        }
    }
    __syncthreads();   // all warps done reading WB (half 1) + H1 fully written

    // stage W2 into WB
    {
        const uint4* src = g_W2img[t];
        for (int i = tid; i < 1632; i += 256) cp16(sb + WB_OFF + i * 16, src + i);
        CP_COMMIT();
        CP_WAIT(0);
    }
    __syncthreads();

    // ===================== LAYER 2: 128 -> 96 (+ fused layer 3) =====================
    float acc2[2][6][4];
    #pragma unroll
    for (int mt = 0; mt < 2; mt++)
        #pragma unroll
        for (int nt = 0; nt < 6; nt++)
            #pragma unroll
            for (int q = 0; q < 4; q++) acc2[mt][nt][q] = 0.f;

    const uint32_t aH1 = sb + H1_OFF + (mb + arow) * 272 + akb;
    const uint32_t bW2 = sb + WB_OFF + (nw * 48 + brow) * 272 + bkb;

    #pragma unroll
    for (int ks = 0; ks < 8; ks++) {
        const uint32_t kb = ks * 32;
        uint32_t A[2][4];
        ldm_x4(A[0], aH1 + kb);
        ldm_x4(A[1], aH1 + 16 * 272 + kb);
        #pragma unroll
        for (int g = 0; g < 3; g++) {
            uint32_t B[4];
            ldm_x4(B, bW2 + g * (16 * 272) + kb);
            #pragma unroll
            for (int s = 0; s < 2; s++) {
                int nt = g * 2 + s;
                #pragma unroll
                for (int mt = 0; mt < 2; mt++)
                    mma_fp16(acc2[mt][nt], A[mt], B + s * 2);
            }
        }
    }

    // layer-3 fused epilogue: e[row] = b3 + sum_col celu(x+b2[col]) * w3[col]
    {
        float part[2][2] = {{0.f, 0.f}, {0.f, 0.f}};
        #pragma unroll
        for (int mt = 0; mt < 2; mt++)
            #pragma unroll
            for (int nt = 0; nt < 6; nt++) {
                int col = nw * 48 + nt * 8 + 2 * (lane & 3);
                float* d = acc2[mt][nt];
                part[mt][0] += celu_f(d[0] + sBias[288 + col]) * sBias[384 + col]
                             + celu_f(d[1] + sBias[288 + col + 1]) * sBias[384 + col + 1];
                part[mt][1] += celu_f(d[2] + sBias[288 + col]) * sBias[384 + col]
                             + celu_f(d[3] + sBias[288 + col + 1]) * sBias[384 + col + 1];
            }
        #pragma unroll
        for (int mt = 0; mt < 2; mt++)
            #pragma unroll
            for (int h = 0; h < 2; h++) {
                part[mt][h] += __shfl_xor_sync(0xffffffffu, part[mt][h], 1);
                part[mt][h] += __shfl_xor_sync(0xffffffffu, part[mt][h], 2);
            }
        if ((lane & 3) == 0) {
            #pragma unroll
            for (int mt = 0; mt < 2; mt++)
                #pragma unroll
                for (int h = 0; h < 2; h++) {
                    int row = mb + mt * 16 + h * 8 + (lane >> 2);
                    atomicAdd(&sE[row], part[mt][h]);
                }
        }
    }
    __syncthreads();
    if (tid < 128) {
        int gi = sIdx[tid];
        if (gi >= 0) g_atom_e[gi] = sE[tid] + sBias[480];
    }
}

// ---------------- output assembly ----------------
__global__ void k_finalize(const int* __restrict__ sp,
                           float* __restrict__ out_head,
                           float* __restrict__ out_e)
{
    int b  = blockIdx.x;
    int tx = threadIdx.x;
    int i  = b * NA + tx;
    float e = g_atom_e[i];
    if (out_head) out_head[i] = (float)get_sp(sp, i, g_is64);
    #pragma unroll
    for (int o = 16; o > 0; o >>= 1) e += __shfl_down_sync(0xffffffffu, e, o);
    __shared__ float s2[2];
    if ((tx & 31) == 0) s2[tx >> 5] = e;
    __syncthreads();
    if (tx == 0) out_e[b] = s2[0] + s2[1];
}

extern "C" void kernel_launch(void* const* d_in, const int* in_sizes, int n_in,
                              void* d_out, int out_size)
{
    const int*   sp  = (const int*)d_in[0];
    const float* aev = (const float*)d_in[1];
    const float* W0 = (const float*)d_in[2];
    const float* b0 = (const float*)d_in[3];
    const float* W1 = (const float*)d_in[4];
    const float* b1 = (const float*)d_in[5];
    const float* W2 = (const float*)d_in[6];
    const float* b2 = (const float*)d_in[7];
    const float* W3 = (const float*)d_in[8];
    const float* b3 = (const float*)d_in[9];

    float* out = (float*)d_out;
    float* out_head;
    float* out_e;
    if (out_size == NB) { out_head = nullptr; out_e = out; }
    else                { out_head = out;     out_e = out + (out_size - NB); }

    k_detect <<<1, 32>>>(sp);
    k_count  <<<NATOMS / 256, 256>>>(sp);
    k_build  <<<1, 1>>>();
    k_scatter<<<NATOMS / 256, 256>>>(sp);
    k_prep   <<<(PREP_TOTAL + 255) / 256, 256>>>(W0, W1, W2);

    cudaFuncSetAttribute(k_mlp_tc, cudaFuncAttributeMaxDynamicSharedMemorySize, SM_TOTAL);
    k_mlp_tc<<<MAXTILES, 256, SM_TOTAL>>>(aev, b0, b1, b2, W3, b3);

    k_finalize<<<NB, NA>>>(sp, out_head, out_e);
}

// round 7
// speedup vs baseline: 5.3798x; 1.1817x over previous
#include <cuda_runtime.h>
#include <cuda_fp16.h>
#include <cstdint>

// ---------------- problem constants ----------------
#define NB      2048
#define NA      64
#define NATOMS  (NB*NA)
#define AEV     384
#define N0      160
#define N1      128
#define N2      96
#define NTYPES  4
#define TILE    128
#define MAXTILES 1040

// ---------------- device scratch ----------------
__device__ int   g_is64;
__device__ int   g_counts[NTYPES];
__device__ int   g_cursor[NTYPES];
__device__ float g_atom_e[NATOMS];
__device__ int   g_perm[NATOMS];

// fp16 weight images, [n][k] layout, padded strides (bytes): W0 208, W1 336, W2 272
__device__ uint4 g_W0img[NTYPES][4][2080];   // per 96-K chunk: 160*208 B
__device__ uint4 g_W1img[NTYPES][2][1344];   // per 64-N half:  64*336 B (K=160)
__device__ uint4 g_W2img[NTYPES][1632];      // 96*272 B (K=128)

__device__ __forceinline__ float celu_f(float x) {
    return x > 0.f ? x : 0.1f * (__expf(10.f * x) - 1.f);
}
__device__ __forceinline__ int get_sp(const int* __restrict__ raw, int i, int is64) {
    return is64 ? raw[2 * i] : raw[i];
}
__device__ __forceinline__ uint32_t pack2h(float a, float b) {
    __half ha = __float2half_rn(a), hb = __float2half_rn(b);
    return (uint32_t)__half_as_ushort(ha) | ((uint32_t)__half_as_ushort(hb) << 16);
}
__device__ __forceinline__ uint32_t smem_u32(const void* p) {
    uint32_t a;
    asm("{ .reg .u64 t; cvta.to.shared.u64 t, %1; cvt.u32.u64 %0, t; }" : "=r"(a) : "l"(p));
    return a;
}
__device__ __forceinline__ void ldm_x4(uint32_t* r, uint32_t addr) {
    asm volatile("ldmatrix.sync.aligned.m8n8.x4.shared.b16 {%0,%1,%2,%3}, [%4];"
                 : "=r"(r[0]), "=r"(r[1]), "=r"(r[2]), "=r"(r[3]) : "r"(addr));
}
__device__ __forceinline__ void mma_fp16(float* d, const uint32_t* a, const uint32_t* b) {
    asm volatile(
        "mma.sync.aligned.m16n8k16.row.col.f32.f16.f16.f32 "
        "{%0,%1,%2,%3},{%4,%5,%6,%7},{%8,%9},{%0,%1,%2,%3};"
        : "+f"(d[0]), "+f"(d[1]), "+f"(d[2]), "+f"(d[3])
        : "r"(a[0]), "r"(a[1]), "r"(a[2]), "r"(a[3]), "r"(b[0]), "r"(b[1]));
}
__device__ __forceinline__ void cp16(uint32_t s, const void* g) {
    asm volatile("cp.async.cg.shared.global [%0], [%1], 16;" :: "r"(s), "l"(g) : "memory");
}
#define CP_COMMIT() asm volatile("cp.async.commit_group;" ::: "memory")
#define CP_WAIT(n)  asm volatile("cp.async.wait_group %0;" :: "n"(n) : "memory")

// ---------------- launch 1: dtype probe + reset ----------------
__global__ void k_detect(const int* __restrict__ sp_raw) {
    if (threadIdx.x == 0) {
        int odd_nonzero = 0;
        #pragma unroll
        for (int i = 1; i < 64; i += 2) odd_nonzero |= (sp_raw[i] != 0);
        g_is64 = odd_nonzero ? 0 : 1;
    }
    if (threadIdx.x < NTYPES) { g_counts[threadIdx.x] = 0; g_cursor[threadIdx.x] = 0; }
}

// ---------------- launch 2: count + weight prep (fused) ----------------
#define PREP_W0 122880   // 4t * 4c * 160n * 48j
#define PREP_W1 40960    // 4t * 2h * 64n * 80j
#define PREP_W2 24576    // 4t * 96n * 64j
#define PREP_TOTAL (PREP_W0 + PREP_W1 + PREP_W2)
#define CP_GRID ((PREP_TOTAL + 255) / 256)   // 738 blocks; covers NATOMS/256=512 too

__global__ void k_count_prep(const int* __restrict__ sp,
                             const float* __restrict__ W0, const float* __restrict__ W1,
                             const float* __restrict__ W2) {
    int gid = blockIdx.x * blockDim.x + threadIdx.x;

    // ---- count part ----
    __shared__ int c[NTYPES];
    if (threadIdx.x < NTYPES) c[threadIdx.x] = 0;
    __syncthreads();
    if (gid < NATOMS) {
        g_atom_e[gid] = 0.f;
        int t = get_sp(sp, gid, g_is64);
        if ((unsigned)t < NTYPES) atomicAdd(&c[t], 1);
    }
    __syncthreads();
    if (threadIdx.x < NTYPES && c[threadIdx.x]) atomicAdd(&g_counts[threadIdx.x], c[threadIdx.x]);

    // ---- prep part ----
    int idx = gid;
    if (idx < PREP_W0) {
        int t = idx / 30720, r = idx % 30720;
        int cc = r / 7680;  r %= 7680;
        int n = r / 48, j = r % 48;
        int k0 = cc * 96 + 2 * j;
        float v0 = W0[((size_t)t * AEV + k0)     * N0 + n];
        float v1 = W0[((size_t)t * AEV + k0 + 1) * N0 + n];
        *(uint32_t*)((char*)g_W0img[t][cc] + n * 208 + j * 4) = pack2h(v0, v1);
    } else if (idx < PREP_W0 + PREP_W1) {
        int i2 = idx - PREP_W0;
        int t = i2 / 10240, r = i2 % 10240;
        int h = r / 5120;  r %= 5120;
        int n = r / 80, j = r % 80;
        int k0 = 2 * j;
        float v0 = W1[((size_t)t * N0 + k0)     * N1 + h * 64 + n];
        float v1 = W1[((size_t)t * N0 + k0 + 1) * N1 + h * 64 + n];
        *(uint32_t*)((char*)g_W1img[t][h] + n * 336 + j * 4) = pack2h(v0, v1);
    } else if (idx < PREP_TOTAL) {
        int i3 = idx - PREP_W0 - PREP_W1;
        int t = i3 / 6144, r = i3 % 6144;
        int n = r / 64, j = r % 64;
        int k0 = 2 * j;
        float v0 = W2[((size_t)t * N1 + k0)     * N2 + n];
        float v1 = W2[((size_t)t * N1 + k0 + 1) * N2 + n];
        *(uint32_t*)((char*)g_W2img[t] + n * 272 + j * 4) = pack2h(v0, v1);
    }
}

// ---------------- launch 3: scatter (offsets derived from counts) ----------------
__global__ void k_scatter(const int* __restrict__ sp) {
    __shared__ int soff[NTYPES];
    __shared__ int base[NTYPES];
    __shared__ int lc[NTYPES];
    if (threadIdx.x == 0) {
        int o = 0;
        #pragma unroll
        for (int t = 0; t < NTYPES; t++) { soff[t] = o; o += g_counts[t]; }
    }
    if (threadIdx.x < NTYPES) lc[threadIdx.x] = 0;
    __syncthreads();
    int i = blockIdx.x * blockDim.x + threadIdx.x;
    int t = -1, r = 0;
    if (i < NATOMS) {
        t = get_sp(sp, i, g_is64);
        if ((unsigned)t < NTYPES) r = atomicAdd(&lc[t], 1); else t = -1;
    }
    __syncthreads();
    if (threadIdx.x < NTYPES)
        base[threadIdx.x] = lc[threadIdx.x] ? atomicAdd(&g_cursor[threadIdx.x], lc[threadIdx.x]) : 0;
    __syncthreads();
    if (t >= 0) g_perm[soff[t] + base[t] + r] = i;
}

// ---------------- launch 4: fused MLP (mma.sync fp16, occupancy 2) ----------------
// SMEM arena (bytes), peak 114176 -> 2 CTAs/SM:
#define BIAS_OFF 0
#define SIDX_OFF 1936
#define SE_OFF   2448
#define WB_OFF   3072
#define X_OFF    36352
#define H1_OFF   36352
#define H0_OFF   71168
#define SM_TOTAL 114176

__global__ __launch_bounds__(256, 2)
void k_mlp_tc(const float* __restrict__ aev,
              const float* __restrict__ b0, const float* __restrict__ b1,
              const float* __restrict__ b2, const float* __restrict__ W3,
              const float* __restrict__ b3)
{
    // derive this CTA's tile (type, start, len) from g_counts
    int t = -1, gstart = 0, len = 0;
    {
        int rem = blockIdx.x, off = 0;
        #pragma unroll
        for (int tt = 0; tt < NTYPES; tt++) {
            int cc = g_counts[tt];
            int ntl = (cc + TILE - 1) / TILE;
            if (t < 0) {
                if (rem < ntl) {
                    t = tt;
                    gstart = off + rem * TILE;
                    int l = cc - rem * TILE;
                    len = l < TILE ? l : TILE;
                } else rem -= ntl;
            }
            off += cc;
        }
    }
    if (t < 0) return;

    extern __shared__ char smem[];
    const uint32_t sb = smem_u32(smem);
    float* sBias = (float*)(smem + BIAS_OFF);
    int*   sIdx  = (int*)(smem + SIDX_OFF);
    float* sE    = (float*)(smem + SE_OFF);

    const int tid  = threadIdx.x;
    const int lane = tid & 31;
    const int w    = tid >> 5;
    const int mb   = (w & 3) * 32;   // warp M base
    const int nw   = (w >> 2);       // warp N group (0/1)

    if (tid < 128) {
        sIdx[tid] = (tid < len) ? g_perm[gstart + tid] : -1;
        sE[tid] = 0.f;
    }
    for (int i = tid; i < N0; i += 256) sBias[i] = b0[t * N0 + i];
    for (int i = tid; i < N1; i += 256) sBias[160 + i] = b1[t * N1 + i];
    for (int i = tid; i < N2; i += 256) { sBias[288 + i] = b2[t * N2 + i]; sBias[384 + i] = W3[t * N2 + i]; }
    if (tid == 0) sBias[480] = b3[t];

    // prefetch W0 chunk 0
    {
        const uint4* src = g_W0img[t][0];
        for (int i = tid; i < 2080; i += 256) cp16(sb + WB_OFF + i * 16, src + i);
        CP_COMMIT();
    }
    __syncthreads();

    // lane offsets for ldmatrix
    const int arow = (lane & 7) + (lane & 8);
    const int akb  = (lane & 16) ? 16 : 0;
    const int brow = (lane & 7) + ((lane & 16) ? 8 : 0);
    const int bkb  = (lane & 8) ? 16 : 0;

    // ===================== LAYER 0: 384 -> 160 =====================
    float acc0[2][10][4];
    #pragma unroll
    for (int mt = 0; mt < 2; mt++)
        #pragma unroll
        for (int nt = 0; nt < 10; nt++)
            #pragma unroll
            for (int q = 0; q < 4; q++) acc0[mt][nt][q] = 0.f;

    const uint32_t aX = sb + X_OFF + (mb + arow) * 208 + akb;
    const uint32_t bW0 = sb + WB_OFF + (nw * 80 + brow) * 208 + bkb;

    for (int c = 0; c < 4; c++) {
        // stage X chunk c: row = tid/2, 48 cols per half-thread, fp16
        {
            int row  = tid >> 1;
            int col0 = (tid & 1) * 48;
            int gi   = sIdx[row];
            const float4* src = (const float4*)(aev + (size_t)(gi < 0 ? 0 : gi) * AEV + c * 96 + col0);
            char* dx = smem + X_OFF + row * 208 + col0 * 2;
            #pragma unroll
            for (int i = 0; i < 12; i++) {
                float4 v = (gi >= 0) ? src[i] : make_float4(0.f, 0.f, 0.f, 0.f);
                *(uint32_t*)(dx + i * 8)     = pack2h(v.x, v.y);
                *(uint32_t*)(dx + i * 8 + 4) = pack2h(v.z, v.w);
            }
        }
        CP_WAIT(0);
        __syncthreads();          // W0 chunk + X ready

        #pragma unroll
        for (int ks = 0; ks < 6; ks++) {
            const uint32_t kb = ks * 32;
            uint32_t A[2][4];
            ldm_x4(A[0], aX + kb);
            ldm_x4(A[1], aX + 16 * 208 + kb);
            uint32_t Bb[2][4];
            ldm_x4(Bb[0], bW0 + kb);
            #pragma unroll
            for (int g = 0; g < 5; g++) {
                uint32_t* Bc = Bb[g & 1];
                if (g < 4) ldm_x4(Bb[(g + 1) & 1], bW0 + (g + 1) * (16 * 208) + kb);
                #pragma unroll
                for (int s = 0; s < 2; s++) {
                    int nt = g * 2 + s;
                    #pragma unroll
                    for (int mt = 0; mt < 2; mt++)
                        mma_fp16(acc0[mt][nt], A[mt], Bc + s * 2);
                }
            }
        }
        __syncthreads();          // all reads of X/WB done before overwrite

        if (c < 3) {              // stage next W0 chunk (overlaps next X staging)
            const uint4* src = g_W0img[t][c + 1];
            for (int i = tid; i < 2080; i += 256) cp16(sb + WB_OFF + i * 16, src + i);
            CP_COMMIT();
        }
    }

    // prefetch W1 half 0 into WB
    {
        const uint4* src = g_W1img[t][0];
        for (int i = tid; i < 1344; i += 256) cp16(sb + WB_OFF + i * 16, src + i);
        CP_COMMIT();
    }

    // epilogue 0 -> H0 (stride 336), celu, fp16
    #pragma unroll
    for (int mt = 0; mt < 2; mt++) {
        int row0 = mb + mt * 16 + (lane >> 2);
        #pragma unroll
        for (int nt = 0; nt < 10; nt++) {
            int col = nw * 80 + nt * 8 + 2 * (lane & 3);
            float* d = acc0[mt][nt];
            float v0 = celu_f(d[0] + sBias[col]);
            float v1 = celu_f(d[1] + sBias[col + 1]);
            float v2 = celu_f(d[2] + sBias[col]);
            float v3 = celu_f(d[3] + sBias[col + 1]);
            *(uint32_t*)(smem + H0_OFF + row0 * 336 + col * 2)       = pack2h(v0, v1);
            *(uint32_t*)(smem + H0_OFF + (row0 + 8) * 336 + col * 2) = pack2h(v2, v3);
        }
    }
    CP_WAIT(0);
    __syncthreads();

    // ===================== LAYER 1: 160 -> 128 (two 64-N halves) =====================
    const uint32_t aH0 = sb + H0_OFF + (mb + arow) * 336 + akb;
    const uint32_t bW1 = sb + WB_OFF + (nw * 32 + brow) * 336 + bkb;

    for (int half = 0; half < 2; half++) {
        float acc1[2][4][4];
        #pragma unroll
        for (int mt = 0; mt < 2; mt++)
            #pragma unroll
            for (int nt = 0; nt < 4; nt++)
                #pragma unroll
                for (int q = 0; q < 4; q++) acc1[mt][nt][q] = 0.f;

        #pragma unroll
        for (int ks = 0; ks < 10; ks++) {
            const uint32_t kb = ks * 32;
            uint32_t A[2][4];
            ldm_x4(A[0], aH0 + kb);
            ldm_x4(A[1], aH0 + 16 * 336 + kb);
            uint32_t Bb[2][4];
            ldm_x4(Bb[0], bW1 + kb);
            #pragma unroll
            for (int g = 0; g < 2; g++) {
                uint32_t* Bc = Bb[g & 1];
                if (g < 1) ldm_x4(Bb[1], bW1 + 16 * 336 + kb);
                #pragma unroll
                for (int s = 0; s < 2; s++) {
                    int nt = g * 2 + s;
                    #pragma unroll
                    for (int mt = 0; mt < 2; mt++)
                        mma_fp16(acc1[mt][nt], A[mt], Bc + s * 2);
                }
            }
        }

        // epilogue 1 -> H1 cols [half*64, half*64+64) (stride 272)
        #pragma unroll
        for (int mt = 0; mt < 2; mt++) {
            int row0 = mb + mt * 16 + (lane >> 2);
            #pragma unroll
            for (int nt = 0; nt < 4; nt++) {
                int col = half * 64 + nw * 32 + nt * 8 + 2 * (lane & 3);
                float* d = acc1[mt][nt];
                float v0 = celu_f(d[0] + sBias[160 + col]);
                float v1 = celu_f(d[1] + sBias[160 + col + 1]);
                float v2 = celu_f(d[2] + sBias[160 + col]);
                float v3 = celu_f(d[3] + sBias[160 + col + 1]);
                *(uint32_t*)(smem + H1_OFF + row0 * 272 + col * 2)       = pack2h(v0, v1);
                *(uint32_t*)(smem + H1_OFF + (row0 + 8) * 272 + col * 2) = pack2h(v2, v3);
            }
        }

        if (half == 0) {   // swap in W1 half 1
            __syncthreads();
            const uint4* src = g_W1img[t][1];
            for (int i = tid; i < 1344; i += 256) cp16(sb + WB_OFF + i * 16, src + i);
            CP_COMMIT();
            CP_WAIT(0);
            __syncthreads();
        }
    }
    __syncthreads();

    // stage W2 into WB
    {
        const uint4* src = g_W2img[t];
        for (int i = tid; i < 1632; i += 256) cp16(sb + WB_OFF + i * 16, src + i);
        CP_COMMIT();
        CP_WAIT(0);
    }
    __syncthreads();

    // ===================== LAYER 2: 128 -> 96 (+ fused layer 3) =====================
    float acc2[2][6][4];
    #pragma unroll
    for (int mt = 0; mt < 2; mt++)
        #pragma unroll
        for (int nt = 0; nt < 6; nt++)
            #pragma unroll
            for (int q = 0; q < 4; q++) acc2[mt][nt][q] = 0.f;

    const uint32_t aH1 = sb + H1_OFF + (mb + arow) * 272 + akb;
    const uint32_t bW2 = sb + WB_OFF + (nw * 48 + brow) * 272 + bkb;

    #pragma unroll
    for (int ks = 0; ks < 8; ks++) {
        const uint32_t kb = ks * 32;
        uint32_t A[2][4];
        ldm_x4(A[0], aH1 + kb);
        ldm_x4(A[1], aH1 + 16 * 272 + kb);
        uint32_t Bb[2][4];
        ldm_x4(Bb[0], bW2 + kb);
        #pragma unroll
        for (int g = 0; g < 3; g++) {
            uint32_t* Bc = Bb[g & 1];
            if (g < 2) ldm_x4(Bb[(g + 1) & 1], bW2 + (g + 1) * (16 * 272) + kb);
            #pragma unroll
            for (int s = 0; s < 2; s++) {
                int nt = g * 2 + s;
                #pragma unroll
                for (int mt = 0; mt < 2; mt++)
                    mma_fp16(acc2[mt][nt], A[mt], Bc + s * 2);
            }
        }
    }

    // layer-3 fused epilogue: e[row] = b3 + sum_col celu(x+b2[col]) * w3[col]
    {
        float part[2][2] = {{0.f, 0.f}, {0.f, 0.f}};
        #pragma unroll
        for (int mt = 0; mt < 2; mt++)
            #pragma unroll
            for (int nt = 0; nt < 6; nt++) {
                int col = nw * 48 + nt * 8 + 2 * (lane & 3);
                float* d = acc2[mt][nt];
                part[mt][0] += celu_f(d[0] + sBias[288 + col]) * sBias[384 + col]
                             + celu_f(d[1] + sBias[288 + col + 1]) * sBias[384 + col + 1];
                part[mt][1] += celu_f(d[2] + sBias[288 + col]) * sBias[384 + col]
                             + celu_f(d[3] + sBias[288 + col + 1]) * sBias[384 + col + 1];
            }
        #pragma unroll
        for (int mt = 0; mt < 2; mt++)
            #pragma unroll
            for (int h = 0; h < 2; h++) {
                part[mt][h] += __shfl_xor_sync(0xffffffffu, part[mt][h], 1);
                part[mt][h] += __shfl_xor_sync(0xffffffffu, part[mt][h], 2);
            }
        if ((lane & 3) == 0) {
            #pragma unroll
            for (int mt = 0; mt < 2; mt++)
                #pragma unroll
                for (int h = 0; h < 2; h++) {
                    int row = mb + mt * 16 + h * 8 + (lane >> 2);
                    atomicAdd(&sE[row], part[mt][h]);
                }
        }
    }
    __syncthreads();
    if (tid < 128) {
        int gi = sIdx[tid];
        if (gi >= 0) g_atom_e[gi] = sE[tid] + sBias[480];
    }
}

// ---------------- launch 5: output assembly ----------------
__global__ void k_finalize(const int* __restrict__ sp,
                           float* __restrict__ out_head,
                           float* __restrict__ out_e)
{
    int b  = blockIdx.x;
    int tx = threadIdx.x;
    int i  = b * NA + tx;
    float e = g_atom_e[i];
    if (out_head) out_head[i] = (float)get_sp(sp, i, g_is64);
    #pragma unroll
    for (int o = 16; o > 0; o >>= 1) e += __shfl_down_sync(0xffffffffu, e, o);
    __shared__ float s2[2];
    if ((tx & 31) == 0) s2[tx >> 5] = e;
    __syncthreads();
    if (tx == 0) out_e[b] = s2[0] + s2[1];
}

extern "C" void kernel_launch(void* const* d_in, const int* in_sizes, int n_in,
                              void* d_out, int out_size)
{
    const int*   sp  = (const int*)d_in[0];
    const float* aev = (const float*)d_in[1];
    const float* W0 = (const float*)d_in[2];
    const float* b0 = (const float*)d_in[3];
    const float* W1 = (const float*)d_in[4];
    const float* b1 = (const float*)d_in[5];
    const float* W2 = (const float*)d_in[6];
    const float* b2 = (const float*)d_in[7];
    const float* W3 = (const float*)d_in[8];
    const float* b3 = (const float*)d_in[9];

    float* out = (float*)d_out;
    float* out_head;
    float* out_e;
    if (out_size == NB) { out_head = nullptr; out_e = out; }
    else                { out_head = out;     out_e = out + (out_size - NB); }

    k_detect    <<<1, 32>>>(sp);
    k_count_prep<<<CP_GRID, 256>>>(sp, W0, W1, W2);
    k_scatter   <<<NATOMS / 256, 256>>>(sp);

    cudaFuncSetAttribute(k_mlp_tc, cudaFuncAttributeMaxDynamicSharedMemorySize, SM_TOTAL);
    k_mlp_tc<<<MAXTILES, 256, SM_TOTAL>>>(aev, b0, b1, b2, W3, b3);

    k_finalize<<<NB, NA>>>(sp, out_head, out_e);
}

// round 8
// speedup vs baseline: 6.5086x; 1.2098x over previous
#include <cuda_runtime.h>
#include <cuda_fp16.h>
#include <cstdint>

// ---------------- problem constants ----------------
#define NB      2048
#define NA      64
#define NATOMS  (NB*NA)
#define AEV     384
#define N0      160
#define N1      128
#define N2      96
#define NTYPES  4
#define TILE    64
#define MAXTILES 2056

// ---------------- device scratch ----------------
__device__ int   g_is64;
__device__ int   g_counts[NTYPES];
__device__ int   g_cursor[NTYPES];
__device__ float g_atom_e[NATOMS];
__device__ int   g_perm[NATOMS];

// fp16 weight images, [n][k] layout, padded strides (bytes): W0 208, W1 336, W2 272
__device__ uint4 g_W0img[NTYPES][4][2080];   // per 96-K chunk: 160*208 B
__device__ uint4 g_W1img[NTYPES][2][1344];   // per 64-N half:  64*336 B (K=160)
__device__ uint4 g_W2img[NTYPES][1632];      // 96*272 B (K=128)

__device__ __forceinline__ float celu_f(float x) {
    return x > 0.f ? x : 0.1f * (__expf(10.f * x) - 1.f);
}
__device__ __forceinline__ int get_sp(const int* __restrict__ raw, int i, int is64) {
    return is64 ? raw[2 * i] : raw[i];
}
__device__ __forceinline__ uint32_t pack2h(float a, float b) {
    __half ha = __float2half_rn(a), hb = __float2half_rn(b);
    return (uint32_t)__half_as_ushort(ha) | ((uint32_t)__half_as_ushort(hb) << 16);
}
__device__ __forceinline__ uint32_t smem_u32(const void* p) {
    uint32_t a;
    asm("{ .reg .u64 t; cvta.to.shared.u64 t, %1; cvt.u32.u64 %0, t; }" : "=r"(a) : "l"(p));
    return a;
}
__device__ __forceinline__ void ldm_x4(uint32_t* r, uint32_t addr) {
    asm volatile("ldmatrix.sync.aligned.m8n8.x4.shared.b16 {%0,%1,%2,%3}, [%4];"
                 : "=r"(r[0]), "=r"(r[1]), "=r"(r[2]), "=r"(r[3]) : "r"(addr));
}
__device__ __forceinline__ void mma_fp16(float* d, const uint32_t* a, const uint32_t* b) {
    asm volatile(
        "mma.sync.aligned.m16n8k16.row.col.f32.f16.f16.f32 "
        "{%0,%1,%2,%3},{%4,%5,%6,%7},{%8,%9},{%0,%1,%2,%3};"
        : "+f"(d[0]), "+f"(d[1]), "+f"(d[2]), "+f"(d[3])
        : "r"(a[0]), "r"(a[1]), "r"(a[2]), "r"(a[3]), "r"(b[0]), "r"(b[1]));
}
__device__ __forceinline__ void cp16(uint32_t s, const void* g) {
    asm volatile("cp.async.cg.shared.global [%0], [%1], 16;" :: "r"(s), "l"(g) : "memory");
}
#define CP_COMMIT() asm volatile("cp.async.commit_group;" ::: "memory")
#define CP_WAIT(n)  asm volatile("cp.async.wait_group %0;" :: "n"(n) : "memory")

// ---------------- launch 1: dtype probe + reset ----------------
__global__ void k_detect(const int* __restrict__ sp_raw) {
    if (threadIdx.x == 0) {
        int odd_nonzero = 0;
        #pragma unroll
        for (int i = 1; i < 64; i += 2) odd_nonzero |= (sp_raw[i] != 0);
        g_is64 = odd_nonzero ? 0 : 1;
    }
    if (threadIdx.x < NTYPES) { g_counts[threadIdx.x] = 0; g_cursor[threadIdx.x] = 0; }
}

// ---------------- launch 2: count + weight prep (fused) ----------------
#define PREP_W0 122880
#define PREP_W1 40960
#define PREP_W2 24576
#define PREP_TOTAL (PREP_W0 + PREP_W1 + PREP_W2)
#define CP_GRID ((PREP_TOTAL + 255) / 256)

__global__ void k_count_prep(const int* __restrict__ sp,
                             const float* __restrict__ W0, const float* __restrict__ W1,
                             const float* __restrict__ W2) {
    int gid = blockIdx.x * blockDim.x + threadIdx.x;

    __shared__ int c[NTYPES];
    if (threadIdx.x < NTYPES) c[threadIdx.x] = 0;
    __syncthreads();
    if (gid < NATOMS) {
        g_atom_e[gid] = 0.f;
        int t = get_sp(sp, gid, g_is64);
        if ((unsigned)t < NTYPES) atomicAdd(&c[t], 1);
    }
    __syncthreads();
    if (threadIdx.x < NTYPES && c[threadIdx.x]) atomicAdd(&g_counts[threadIdx.x], c[threadIdx.x]);

    int idx = gid;
    if (idx < PREP_W0) {
        int t = idx / 30720, r = idx % 30720;
        int cc = r / 7680;  r %= 7680;
        int n = r / 48, j = r % 48;
        int k0 = cc * 96 + 2 * j;
        float v0 = W0[((size_t)t * AEV + k0)     * N0 + n];
        float v1 = W0[((size_t)t * AEV + k0 + 1) * N0 + n];
        *(uint32_t*)((char*)g_W0img[t][cc] + n * 208 + j * 4) = pack2h(v0, v1);
    } else if (idx < PREP_W0 + PREP_W1) {
        int i2 = idx - PREP_W0;
        int t = i2 / 10240, r = i2 % 10240;
        int h = r / 5120;  r %= 5120;
        int n = r / 80, j = r % 80;
        int k0 = 2 * j;
        float v0 = W1[((size_t)t * N0 + k0)     * N1 + h * 64 + n];
        float v1 = W1[((size_t)t * N0 + k0 + 1) * N1 + h * 64 + n];
        *(uint32_t*)((char*)g_W1img[t][h] + n * 336 + j * 4) = pack2h(v0, v1);
    } else if (idx < PREP_TOTAL) {
        int i3 = idx - PREP_W0 - PREP_W1;
        int t = i3 / 6144, r = i3 % 6144;
        int n = r / 64, j = r % 64;
        int k0 = 2 * j;
        float v0 = W2[((size_t)t * N1 + k0)     * N2 + n];
        float v1 = W2[((size_t)t * N1 + k0 + 1) * N2 + n];
        *(uint32_t*)((char*)g_W2img[t] + n * 272 + j * 4) = pack2h(v0, v1);
    }
}

// ---------------- launch 3: scatter ----------------
__global__ void k_scatter(const int* __restrict__ sp) {
    __shared__ int soff[NTYPES];
    __shared__ int base[NTYPES];
    __shared__ int lc[NTYPES];
    if (threadIdx.x == 0) {
        int o = 0;
        #pragma unroll
        for (int t = 0; t < NTYPES; t++) { soff[t] = o; o += g_counts[t]; }
    }
    if (threadIdx.x < NTYPES) lc[threadIdx.x] = 0;
    __syncthreads();
    int i = blockIdx.x * blockDim.x + threadIdx.x;
    int t = -1, r = 0;
    if (i < NATOMS) {
        t = get_sp(sp, i, g_is64);
        if ((unsigned)t < NTYPES) r = atomicAdd(&lc[t], 1); else t = -1;
    }
    __syncthreads();
    if (threadIdx.x < NTYPES)
        base[threadIdx.x] = lc[threadIdx.x] ? atomicAdd(&g_cursor[threadIdx.x], lc[threadIdx.x]) : 0;
    __syncthreads();
    if (t >= 0) g_perm[soff[t] + base[t] + r] = i;
}

// ---------------- launch 4: fused MLP (64-atom tiles, 3 CTAs/SM) ----------------
// SMEM arena (bytes), peak 74752:
//   BIAS @ 0      : 481 floats (1936)
//   SIDX @ 1936   : 256
//   SE   @ 2192   : 256 (pad to 2560)
//   WB   @ 2560   : 33280  (W0 chunk -> W1 half -> W2)
//   X    @ 35840  : 13312  (L0 A; dead after L0)
//   H1   @ 35840  : 17408  (over X; L1 out, L2 in)
//   H0   @ 53248  : 21504  (L0 out, L1 in)
#define BIAS_OFF 0
#define SIDX_OFF 1936
#define SE_OFF   2192
#define WB_OFF   2560
#define X_OFF    35840
#define H1_OFF   35840
#define H0_OFF   53248
#define SM_TOTAL 74752

__global__ __launch_bounds__(256, 3)
void k_mlp_tc(const float* __restrict__ aev,
              const float* __restrict__ b0, const float* __restrict__ b1,
              const float* __restrict__ b2, const float* __restrict__ W3,
              const float* __restrict__ b3)
{
    // derive this CTA's tile (type, start, len) from g_counts
    int t = -1, gstart = 0, len = 0;
    {
        int rem = blockIdx.x, off = 0;
        #pragma unroll
        for (int tt = 0; tt < NTYPES; tt++) {
            int cc = g_counts[tt];
            int ntl = (cc + TILE - 1) / TILE;
            if (t < 0) {
                if (rem < ntl) {
                    t = tt;
                    gstart = off + rem * TILE;
                    int l = cc - rem * TILE;
                    len = l < TILE ? l : TILE;
                } else rem -= ntl;
            }
            off += cc;
        }
    }
    if (t < 0) return;

    extern __shared__ char smem[];
    const uint32_t sb = smem_u32(smem);
    float* sBias = (float*)(smem + BIAS_OFF);
    int*   sIdx  = (int*)(smem + SIDX_OFF);
    float* sE    = (float*)(smem + SE_OFF);

    const int tid  = threadIdx.x;
    const int lane = tid & 31;
    const int w    = tid >> 5;
    const int mb   = (w & 3) * 16;   // warp M base (16 rows per warp)
    const int nw   = (w >> 2);       // warp N group (0/1)

    if (tid < TILE) {
        sIdx[tid] = (tid < len) ? g_perm[gstart + tid] : -1;
        sE[tid] = 0.f;
    }
    for (int i = tid; i < N0; i += 256) sBias[i] = b0[t * N0 + i];
    for (int i = tid; i < N1; i += 256) sBias[160 + i] = b1[t * N1 + i];
    for (int i = tid; i < N2; i += 256) { sBias[288 + i] = b2[t * N2 + i]; sBias[384 + i] = W3[t * N2 + i]; }
    if (tid == 0) sBias[480] = b3[t];

    // prefetch W0 chunk 0
    {
        const uint4* src = g_W0img[t][0];
        for (int i = tid; i < 2080; i += 256) cp16(sb + WB_OFF + i * 16, src + i);
        CP_COMMIT();
    }
    __syncthreads();

    // lane offsets for ldmatrix
    const int arow = (lane & 7) + (lane & 8);
    const int akb  = (lane & 16) ? 16 : 0;
    const int brow = (lane & 7) + ((lane & 16) ? 8 : 0);
    const int bkb  = (lane & 8) ? 16 : 0;

    // ===================== LAYER 0: 384 -> 160 =====================
    float acc0[10][4];
    #pragma unroll
    for (int nt = 0; nt < 10; nt++)
        #pragma unroll
        for (int q = 0; q < 4; q++) acc0[nt][q] = 0.f;

    const uint32_t aX  = sb + X_OFF + (mb + arow) * 208 + akb;
    const uint32_t bW0 = sb + WB_OFF + (nw * 80 + brow) * 208 + bkb;

    for (int c = 0; c < 4; c++) {
        // stage X chunk c: row = tid/4 (0..63), 24 cols per quarter-thread
        {
            int row  = tid >> 2;
            int col0 = (tid & 3) * 24;
            int gi   = sIdx[row];
            const float4* src = (const float4*)(aev + (size_t)(gi < 0 ? 0 : gi) * AEV + c * 96 + col0);
            char* dx = smem + X_OFF + row * 208 + col0 * 2;
            #pragma unroll
            for (int i = 0; i < 6; i++) {
                float4 v = (gi >= 0) ? src[i] : make_float4(0.f, 0.f, 0.f, 0.f);
                *(uint32_t*)(dx + i * 8)     = pack2h(v.x, v.y);
                *(uint32_t*)(dx + i * 8 + 4) = pack2h(v.z, v.w);
            }
        }
        CP_WAIT(0);
        __syncthreads();          // W0 chunk + X ready

        #pragma unroll
        for (int ks = 0; ks < 6; ks++) {
            const uint32_t kb = ks * 32;
            uint32_t A[4];
            ldm_x4(A, aX + kb);
            uint32_t Bb[2][4];
            ldm_x4(Bb[0], bW0 + kb);
            #pragma unroll
            for (int g = 0; g < 5; g++) {
                uint32_t* Bc = Bb[g & 1];
                if (g < 4) ldm_x4(Bb[(g + 1) & 1], bW0 + (g + 1) * (16 * 208) + kb);
                #pragma unroll
                for (int s = 0; s < 2; s++)
                    mma_fp16(acc0[g * 2 + s], A, Bc + s * 2);
            }
        }
        __syncthreads();          // all reads of X/WB done before overwrite

        if (c < 3) {
            const uint4* src = g_W0img[t][c + 1];
            for (int i = tid; i < 2080; i += 256) cp16(sb + WB_OFF + i * 16, src + i);
            CP_COMMIT();
        }
    }

    // prefetch W1 half 0 into WB
    {
        const uint4* src = g_W1img[t][0];
        for (int i = tid; i < 1344; i += 256) cp16(sb + WB_OFF + i * 16, src + i);
        CP_COMMIT();
    }

    // epilogue 0 -> H0 (stride 336), celu, fp16
    {
        int row0 = mb + (lane >> 2);
        #pragma unroll
        for (int nt = 0; nt < 10; nt++) {
            int col = nw * 80 + nt * 8 + 2 * (lane & 3);
            float* d = acc0[nt];
            float v0 = celu_f(d[0] + sBias[col]);
            float v1 = celu_f(d[1] + sBias[col + 1]);
            float v2 = celu_f(d[2] + sBias[col]);
            float v3 = celu_f(d[3] + sBias[col + 1]);
            *(uint32_t*)(smem + H0_OFF + row0 * 336 + col * 2)       = pack2h(v0, v1);
            *(uint32_t*)(smem + H0_OFF + (row0 + 8) * 336 + col * 2) = pack2h(v2, v3);
        }
    }
    CP_WAIT(0);
    __syncthreads();

    // ===================== LAYER 1: 160 -> 128 (two 64-N halves) =====================
    const uint32_t aH0 = sb + H0_OFF + (mb + arow) * 336 + akb;
    const uint32_t bW1 = sb + WB_OFF + (nw * 32 + brow) * 336 + bkb;

    for (int half = 0; half < 2; half++) {
        float acc1[4][4];
        #pragma unroll
        for (int nt = 0; nt < 4; nt++)
            #pragma unroll
            for (int q = 0; q < 4; q++) acc1[nt][q] = 0.f;

        #pragma unroll
        for (int ks = 0; ks < 10; ks++) {
            const uint32_t kb = ks * 32;
            uint32_t A[4];
            ldm_x4(A, aH0 + kb);
            uint32_t Bb[2][4];
            ldm_x4(Bb[0], bW1 + kb);
            #pragma unroll
            for (int g = 0; g < 2; g++) {
                uint32_t* Bc = Bb[g & 1];
                if (g < 1) ldm_x4(Bb[1], bW1 + 16 * 336 + kb);
                #pragma unroll
                for (int s = 0; s < 2; s++)
                    mma_fp16(acc1[g * 2 + s], A, Bc + s * 2);
            }
        }

        // epilogue 1 -> H1 cols [half*64, half*64+64) (stride 272)
        {
            int row0 = mb + (lane >> 2);
            #pragma unroll
            for (int nt = 0; nt < 4; nt++) {
                int col = half * 64 + nw * 32 + nt * 8 + 2 * (lane & 3);
                float* d = acc1[nt];
                float v0 = celu_f(d[0] + sBias[160 + col]);
                float v1 = celu_f(d[1] + sBias[160 + col + 1]);
                float v2 = celu_f(d[2] + sBias[160 + col]);
                float v3 = celu_f(d[3] + sBias[160 + col + 1]);
                *(uint32_t*)(smem + H1_OFF + row0 * 272 + col * 2)       = pack2h(v0, v1);
                *(uint32_t*)(smem + H1_OFF + (row0 + 8) * 272 + col * 2) = pack2h(v2, v3);
            }
        }

        if (half == 0) {   // swap in W1 half 1
            __syncthreads();
            const uint4* src = g_W1img[t][1];
            for (int i = tid; i < 1344; i += 256) cp16(sb + WB_OFF + i * 16, src + i);
            CP_COMMIT();
            CP_WAIT(0);
            __syncthreads();
        }
    }
    __syncthreads();

    // stage W2 into WB
    {
        const uint4* src = g_W2img[t];
        for (int i = tid; i < 1632; i += 256) cp16(sb + WB_OFF + i * 16, src + i);
        CP_COMMIT();
        CP_WAIT(0);
    }
    __syncthreads();

    // ===================== LAYER 2: 128 -> 96 (+ fused layer 3) =====================
    float acc2[6][4];
    #pragma unroll
    for (int nt = 0; nt < 6; nt++)
        #pragma unroll
        for (int q = 0; q < 4; q++) acc2[nt][q] = 0.f;

    const uint32_t aH1 = sb + H1_OFF + (mb + arow) * 272 + akb;
    const uint32_t bW2 = sb + WB_OFF + (nw * 48 + brow) * 272 + bkb;

    #pragma unroll
    for (int ks = 0; ks < 8; ks++) {
        const uint32_t kb = ks * 32;
        uint32_t A[4];
        ldm_x4(A, aH1 + kb);
        uint32_t Bb[2][4];
        ldm_x4(Bb[0], bW2 + kb);
        #pragma unroll
        for (int g = 0; g < 3; g++) {
            uint32_t* Bc = Bb[g & 1];
            if (g < 2) ldm_x4(Bb[(g + 1) & 1], bW2 + (g + 1) * (16 * 272) + kb);
            #pragma unroll
            for (int s = 0; s < 2; s++)
                mma_fp16(acc2[g * 2 + s], A, Bc + s * 2);
        }
    }

    // layer-3 fused epilogue: e[row] = b3 + sum_col celu(x+b2[col]) * w3[col]
    {
        float part[2] = {0.f, 0.f};
        #pragma unroll
        for (int nt = 0; nt < 6; nt++) {
            int col = nw * 48 + nt * 8 + 2 * (lane & 3);
            float* d = acc2[nt];
            part[0] += celu_f(d[0] + sBias[288 + col]) * sBias[384 + col]
                     + celu_f(d[1] + sBias[288 + col + 1]) * sBias[384 + col + 1];
            part[1] += celu_f(d[2] + sBias[288 + col]) * sBias[384 + col]
                     + celu_f(d[3] + sBias[288 + col + 1]) * sBias[384 + col + 1];
        }
        #pragma unroll
        for (int h = 0; h < 2; h++) {
            part[h] += __shfl_xor_sync(0xffffffffu, part[h], 1);
            part[h] += __shfl_xor_sync(0xffffffffu, part[h], 2);
        }
        if ((lane & 3) == 0) {
            #pragma unroll
            for (int h = 0; h < 2; h++) {
                int row = mb + h * 8 + (lane >> 2);
                atomicAdd(&sE[row], part[h]);
            }
        }
    }
    __syncthreads();
    if (tid < TILE) {
        int gi = sIdx[tid];
        if (gi >= 0) g_atom_e[gi] = sE[tid] + sBias[480];
    }
}

// ---------------- launch 5: output assembly ----------------
__global__ void k_finalize(const int* __restrict__ sp,
                           float* __restrict__ out_head,
                           float* __restrict__ out_e)
{
    int b  = blockIdx.x;
    int tx = threadIdx.x;
    int i  = b * NA + tx;
    float e = g_atom_e[i];
    if (out_head) out_head[i] = (float)get_sp(sp, i, g_is64);
    #pragma unroll
    for (int o = 16; o > 0; o >>= 1) e += __shfl_down_sync(0xffffffffu, e, o);
    __shared__ float s2[2];
    if ((tx & 31) == 0) s2[tx >> 5] = e;
    __syncthreads();
    if (tx == 0) out_e[b] = s2[0] + s2[1];
}

extern "C" void kernel_launch(void* const* d_in, const int* in_sizes, int n_in,
                              void* d_out, int out_size)
{
    const int*   sp  = (const int*)d_in[0];
    const float* aev = (const float*)d_in[1];
    const float* W0 = (const float*)d_in[2];
    const float* b0 = (const float*)d_in[3];
    const float* W1 = (const float*)d_in[4];
    const float* b1 = (const float*)d_in[5];
    const float* W2 = (const float*)d_in[6];
    const float* b2 = (const float*)d_in[7];
    const float* W3 = (const float*)d_in[8];
    const float* b3 = (const float*)d_in[9];

    float* out = (float*)d_out;
    float* out_head;
    float* out_e;
    if (out_size == NB) { out_head = nullptr; out_e = out; }
    else                { out_head = out;     out_e = out + (out_size - NB); }

    k_detect    <<<1, 32>>>(sp);
    k_count_prep<<<CP_GRID, 256>>>(sp, W0, W1, W2);
    k_scatter   <<<NATOMS / 256, 256>>>(sp);

    cudaFuncSetAttribute(k_mlp_tc, cudaFuncAttributeMaxDynamicSharedMemorySize, SM_TOTAL);
    k_mlp_tc<<<MAXTILES, 256, SM_TOTAL>>>(aev, b0, b1, b2, W3, b3);

    k_finalize<<<NB, NA>>>(sp, out_head, out_e);
}

// round 9
// speedup vs baseline: 6.6388x; 1.0200x over previous
#include <cuda_runtime.h>
#include <cuda_fp16.h>
#include <cstdint>

// ---------------- problem constants ----------------
#define NB      2048
#define NA      64
#define NATOMS  (NB*NA)
#define AEV     384
#define N0      160
#define N1      128
#define N2      96
#define NTYPES  4
#define TILE    64
#define MAXTILES 2056

// ---------------- device scratch ----------------
__device__ int   g_is64;
__device__ int   g_counts[NTYPES];
__device__ int   g_cursor[NTYPES];
__device__ float g_atom_e[NATOMS];
__device__ int   g_perm[NATOMS];

// fp16 weight images, [n][k] layout, padded strides (bytes): W0 208, W1 336, W2 272
__device__ uint4 g_W0img[NTYPES][4][2080];   // per 96-K chunk: 160*208 B
__device__ uint4 g_W1img[NTYPES][2][1344];   // per 64-N half:  64*336 B (K=160)
__device__ uint4 g_W2img[NTYPES][1632];      // 96*272 B (K=128)

__device__ __forceinline__ float celu_f(float x) {
    return x > 0.f ? x : 0.1f * (__expf(10.f * x) - 1.f);
}
__device__ __forceinline__ int get_sp(const int* __restrict__ raw, int i, int is64) {
    return is64 ? raw[2 * i] : raw[i];
}
__device__ __forceinline__ uint32_t pack2h(float a, float b) {
    __half ha = __float2half_rn(a), hb = __float2half_rn(b);
    return (uint32_t)__half_as_ushort(ha) | ((uint32_t)__half_as_ushort(hb) << 16);
}
__device__ __forceinline__ uint32_t smem_u32(const void* p) {
    uint32_t a;
    asm("{ .reg .u64 t; cvta.to.shared.u64 t, %1; cvt.u32.u64 %0, t; }" : "=r"(a) : "l"(p));
    return a;
}
__device__ __forceinline__ void ldm_x4(uint32_t* r, uint32_t addr) {
    asm volatile("ldmatrix.sync.aligned.m8n8.x4.shared.b16 {%0,%1,%2,%3}, [%4];"
                 : "=r"(r[0]), "=r"(r[1]), "=r"(r[2]), "=r"(r[3]) : "r"(addr));
}
__device__ __forceinline__ void ldm_x2(uint32_t* r, uint32_t addr) {
    asm volatile("ldmatrix.sync.aligned.m8n8.x2.shared.b16 {%0,%1}, [%2];"
                 : "=r"(r[0]), "=r"(r[1]) : "r"(addr));
}
__device__ __forceinline__ void mma_fp16(float* d, const uint32_t* a, const uint32_t* b) {
    asm volatile(
        "mma.sync.aligned.m16n8k16.row.col.f32.f16.f16.f32 "
        "{%0,%1,%2,%3},{%4,%5,%6,%7},{%8,%9},{%0,%1,%2,%3};"
        : "+f"(d[0]), "+f"(d[1]), "+f"(d[2]), "+f"(d[3])
        : "r"(a[0]), "r"(a[1]), "r"(a[2]), "r"(a[3]), "r"(b[0]), "r"(b[1]));
}
__device__ __forceinline__ void cp16(uint32_t s, const void* g) {
    asm volatile("cp.async.cg.shared.global [%0], [%1], 16;" :: "r"(s), "l"(g) : "memory");
}
#define CP_COMMIT() asm volatile("cp.async.commit_group;" ::: "memory")
#define CP_WAIT(n)  asm volatile("cp.async.wait_group %0;" :: "n"(n) : "memory")

// ---------------- launch 1: dtype probe + reset ----------------
__global__ void k_detect(const int* __restrict__ sp_raw) {
    if (threadIdx.x == 0) {
        int odd_nonzero = 0;
        #pragma unroll
        for (int i = 1; i < 64; i += 2) odd_nonzero |= (sp_raw[i] != 0);
        g_is64 = odd_nonzero ? 0 : 1;
    }
    if (threadIdx.x < NTYPES) { g_counts[threadIdx.x] = 0; g_cursor[threadIdx.x] = 0; }
}

// ---------------- launch 2: count + weight prep (fused) ----------------
#define PREP_W0 122880
#define PREP_W1 40960
#define PREP_W2 24576
#define PREP_TOTAL (PREP_W0 + PREP_W1 + PREP_W2)
#define CP_GRID ((PREP_TOTAL + 255) / 256)

__global__ void k_count_prep(const int* __restrict__ sp,
                             const float* __restrict__ W0, const float* __restrict__ W1,
                             const float* __restrict__ W2) {
    int gid = blockIdx.x * blockDim.x + threadIdx.x;

    __shared__ int c[NTYPES];
    if (threadIdx.x < NTYPES) c[threadIdx.x] = 0;
    __syncthreads();
    if (gid < NATOMS) {
        g_atom_e[gid] = 0.f;
        int t = get_sp(sp, gid, g_is64);
        if ((unsigned)t < NTYPES) atomicAdd(&c[t], 1);
    }
    __syncthreads();
    if (threadIdx.x < NTYPES && c[threadIdx.x]) atomicAdd(&g_counts[threadIdx.x], c[threadIdx.x]);

    int idx = gid;
    if (idx < PREP_W0) {
        int t = idx / 30720, r = idx % 30720;
        int cc = r / 7680;  r %= 7680;
        int n = r / 48, j = r % 48;
        int k0 = cc * 96 + 2 * j;
        float v0 = W0[((size_t)t * AEV + k0)     * N0 + n];
        float v1 = W0[((size_t)t * AEV + k0 + 1) * N0 + n];
        *(uint32_t*)((char*)g_W0img[t][cc] + n * 208 + j * 4) = pack2h(v0, v1);
    } else if (idx < PREP_W0 + PREP_W1) {
        int i2 = idx - PREP_W0;
        int t = i2 / 10240, r = i2 % 10240;
        int h = r / 5120;  r %= 5120;
        int n = r / 80, j = r % 80;
        int k0 = 2 * j;
        float v0 = W1[((size_t)t * N0 + k0)     * N1 + h * 64 + n];
        float v1 = W1[((size_t)t * N0 + k0 + 1) * N1 + h * 64 + n];
        *(uint32_t*)((char*)g_W1img[t][h] + n * 336 + j * 4) = pack2h(v0, v1);
    } else if (idx < PREP_TOTAL) {
        int i3 = idx - PREP_W0 - PREP_W1;
        int t = i3 / 6144, r = i3 % 6144;
        int n = r / 64, j = r % 64;
        int k0 = 2 * j;
        float v0 = W2[((size_t)t * N1 + k0)     * N2 + n];
        float v1 = W2[((size_t)t * N1 + k0 + 1) * N2 + n];
        *(uint32_t*)((char*)g_W2img[t] + n * 272 + j * 4) = pack2h(v0, v1);
    }
}

// ---------------- launch 3: scatter ----------------
__global__ void k_scatter(const int* __restrict__ sp) {
    __shared__ int soff[NTYPES];
    __shared__ int base[NTYPES];
    __shared__ int lc[NTYPES];
    if (threadIdx.x == 0) {
        int o = 0;
        #pragma unroll
        for (int t = 0; t < NTYPES; t++) { soff[t] = o; o += g_counts[t]; }
    }
    if (threadIdx.x < NTYPES) lc[threadIdx.x] = 0;
    __syncthreads();
    int i = blockIdx.x * blockDim.x + threadIdx.x;
    int t = -1, r = 0;
    if (i < NATOMS) {
        t = get_sp(sp, i, g_is64);
        if ((unsigned)t < NTYPES) r = atomicAdd(&lc[t], 1); else t = -1;
    }
    __syncthreads();
    if (threadIdx.x < NTYPES)
        base[threadIdx.x] = lc[threadIdx.x] ? atomicAdd(&g_cursor[threadIdx.x], lc[threadIdx.x]) : 0;
    __syncthreads();
    if (t >= 0) g_perm[soff[t] + base[t] + r] = i;
}

// ---------------- launch 4: fused MLP (64-atom tiles, 2Mx4N warps, A-pipelined) ----------------
#define BIAS_OFF 0
#define SIDX_OFF 1936
#define SE_OFF   2192
#define WB_OFF   2560
#define X_OFF    35840
#define H1_OFF   35840
#define H0_OFF   53248
#define SM_TOTAL 74752

__global__ __launch_bounds__(256, 3)
void k_mlp_tc(const float* __restrict__ aev,
              const float* __restrict__ b0, const float* __restrict__ b1,
              const float* __restrict__ b2, const float* __restrict__ W3,
              const float* __restrict__ b3)
{
    // derive this CTA's tile (type, start, len) from g_counts
    int t = -1, gstart = 0, len = 0;
    {
        int rem = blockIdx.x, off = 0;
        #pragma unroll
        for (int tt = 0; tt < NTYPES; tt++) {
            int cc = g_counts[tt];
            int ntl = (cc + TILE - 1) / TILE;
            if (t < 0) {
                if (rem < ntl) {
                    t = tt;
                    gstart = off + rem * TILE;
                    int l = cc - rem * TILE;
                    len = l < TILE ? l : TILE;
                } else rem -= ntl;
            }
            off += cc;
        }
    }
    if (t < 0) return;

    extern __shared__ char smem[];
    const uint32_t sb = smem_u32(smem);
    float* sBias = (float*)(smem + BIAS_OFF);
    int*   sIdx  = (int*)(smem + SIDX_OFF);
    float* sE    = (float*)(smem + SE_OFF);

    const int tid  = threadIdx.x;
    const int lane = tid & 31;
    const int w    = tid >> 5;
    const int mw   = w & 1;         // M group (0/1): rows mw*32..mw*32+31 (2 m16 tiles)
    const int nww  = w >> 1;        // N group (0..3)
    const int mb   = mw * 32;

    if (tid < TILE) {
        sIdx[tid] = (tid < len) ? g_perm[gstart + tid] : -1;
        sE[tid] = 0.f;
    }
    for (int i = tid; i < N0; i += 256) sBias[i] = b0[t * N0 + i];
    for (int i = tid; i < N1; i += 256) sBias[160 + i] = b1[t * N1 + i];
    for (int i = tid; i < N2; i += 256) { sBias[288 + i] = b2[t * N2 + i]; sBias[384 + i] = W3[t * N2 + i]; }
    if (tid == 0) sBias[480] = b3[t];

    // prefetch W0 chunk 0
    {
        const uint4* src = g_W0img[t][0];
        for (int i = tid; i < 2080; i += 256) cp16(sb + WB_OFF + i * 16, src + i);
        CP_COMMIT();
    }
    __syncthreads();

    // lane offsets for ldmatrix
    const int arow  = (lane & 7) + (lane & 8);
    const int akb   = (lane & 16) ? 16 : 0;
    const int brow  = (lane & 7) + ((lane & 16) ? 8 : 0);
    const int bkb   = (lane & 8) ? 16 : 0;
    const int brow2 = (lane & 7);               // x2 B (n8k16)
    const int bkb2  = (lane & 8) ? 16 : 0;

    // ===================== LAYER 0: 384 -> 160 =====================
    float acc0[2][5][4];
    #pragma unroll
    for (int mt = 0; mt < 2; mt++)
        #pragma unroll
        for (int nt = 0; nt < 5; nt++)
            #pragma unroll
            for (int q = 0; q < 4; q++) acc0[mt][nt][q] = 0.f;

    const uint32_t aX  = sb + X_OFF + (mb + arow) * 208 + akb;
    const uint32_t bA0 = sb + WB_OFF + (nww * 40 + brow) * 208 + bkb;           // n16 @ +0
    const uint32_t bB0 = bA0 + 16 * 208;                                         // n16 @ +16
    const uint32_t bC0 = sb + WB_OFF + (nww * 40 + 32 + brow2) * 208 + bkb2;     // n8  @ +32

    for (int c = 0; c < 4; c++) {
        // stage X chunk c: row = tid/4 (0..63), 24 cols per quarter-thread
        {
            int row  = tid >> 2;
            int col0 = (tid & 3) * 24;
            int gi   = sIdx[row];
            const float4* src = (const float4*)(aev + (size_t)(gi < 0 ? 0 : gi) * AEV + c * 96 + col0);
            char* dx = smem + X_OFF + row * 208 + col0 * 2;
            #pragma unroll
            for (int i = 0; i < 6; i++) {
                float4 v = (gi >= 0) ? src[i] : make_float4(0.f, 0.f, 0.f, 0.f);
                *(uint32_t*)(dx + i * 8)     = pack2h(v.x, v.y);
                *(uint32_t*)(dx + i * 8 + 4) = pack2h(v.z, v.w);
            }
        }
        CP_WAIT(0);
        __syncthreads();          // W0 chunk + X ready

        uint32_t Ab[2][2][4];
        ldm_x4(Ab[0][0], aX);
        ldm_x4(Ab[0][1], aX + 16 * 208);
        #pragma unroll
        for (int ks = 0; ks < 6; ks++) {
            const uint32_t kb = ks * 32;
            const int cur = ks & 1;
            uint32_t B0[4], B1[4], B2[2];
            ldm_x4(B0, bA0 + kb);
            ldm_x4(B1, bB0 + kb);
            ldm_x2(B2, bC0 + kb);
            if (ks < 5) {         // prefetch A for next ks
                ldm_x4(Ab[cur ^ 1][0], aX + kb + 32);
                ldm_x4(Ab[cur ^ 1][1], aX + 16 * 208 + kb + 32);
            }
            #pragma unroll
            for (int mt = 0; mt < 2; mt++) {
                mma_fp16(acc0[mt][0], Ab[cur][mt], B0);
                mma_fp16(acc0[mt][1], Ab[cur][mt], B0 + 2);
                mma_fp16(acc0[mt][2], Ab[cur][mt], B1);
                mma_fp16(acc0[mt][3], Ab[cur][mt], B1 + 2);
                mma_fp16(acc0[mt][4], Ab[cur][mt], B2);
            }
        }
        __syncthreads();          // all reads of X/WB done before overwrite

        if (c < 3) {
            const uint4* src = g_W0img[t][c + 1];
            for (int i = tid; i < 2080; i += 256) cp16(sb + WB_OFF + i * 16, src + i);
            CP_COMMIT();
        }
    }

    // prefetch W1 half 0 into WB
    {
        const uint4* src = g_W1img[t][0];
        for (int i = tid; i < 1344; i += 256) cp16(sb + WB_OFF + i * 16, src + i);
        CP_COMMIT();
    }

    // epilogue 0 -> H0 (stride 336), celu, fp16
    #pragma unroll
    for (int mt = 0; mt < 2; mt++) {
        int row0 = mb + mt * 16 + (lane >> 2);
        #pragma unroll
        for (int nt = 0; nt < 5; nt++) {
            int col = nww * 40 + nt * 8 + 2 * (lane & 3);
            float* d = acc0[mt][nt];
            float v0 = celu_f(d[0] + sBias[col]);
            float v1 = celu_f(d[1] + sBias[col + 1]);
            float v2 = celu_f(d[2] + sBias[col]);
            float v3 = celu_f(d[3] + sBias[col + 1]);
            *(uint32_t*)(smem + H0_OFF + row0 * 336 + col * 2)       = pack2h(v0, v1);
            *(uint32_t*)(smem + H0_OFF + (row0 + 8) * 336 + col * 2) = pack2h(v2, v3);
        }
    }
    CP_WAIT(0);
    __syncthreads();

    // ===================== LAYER 1: 160 -> 128 (two 64-N halves) =====================
    const uint32_t aH0 = sb + H0_OFF + (mb + arow) * 336 + akb;
    const uint32_t bW1 = sb + WB_OFF + (nww * 16 + brow) * 336 + bkb;   // n16 per warp per half

    for (int half = 0; half < 2; half++) {
        float acc1[2][2][4];
        #pragma unroll
        for (int mt = 0; mt < 2; mt++)
            #pragma unroll
            for (int nt = 0; nt < 2; nt++)
                #pragma unroll
                for (int q = 0; q < 4; q++) acc1[mt][nt][q] = 0.f;

        uint32_t Ab[2][2][4], Bb[2][4];
        ldm_x4(Ab[0][0], aH0);
        ldm_x4(Ab[0][1], aH0 + 16 * 336);
        ldm_x4(Bb[0], bW1);
        #pragma unroll
        for (int ks = 0; ks < 10; ks++) {
            const int cur = ks & 1;
            if (ks < 9) {
                const uint32_t kb2 = (ks + 1) * 32;
                ldm_x4(Ab[cur ^ 1][0], aH0 + kb2);
                ldm_x4(Ab[cur ^ 1][1], aH0 + 16 * 336 + kb2);
                ldm_x4(Bb[cur ^ 1], bW1 + kb2);
            }
            #pragma unroll
            for (int mt = 0; mt < 2; mt++) {
                mma_fp16(acc1[mt][0], Ab[cur][mt], Bb[cur]);
                mma_fp16(acc1[mt][1], Ab[cur][mt], Bb[cur] + 2);
            }
        }

        // epilogue 1 -> H1 cols [half*64 + nww*16, +16) (stride 272)
        #pragma unroll
        for (int mt = 0; mt < 2; mt++) {
            int row0 = mb + mt * 16 + (lane >> 2);
            #pragma unroll
            for (int nt = 0; nt < 2; nt++) {
                int col = half * 64 + nww * 16 + nt * 8 + 2 * (lane & 3);
                float* d = acc1[mt][nt];
                float v0 = celu_f(d[0] + sBias[160 + col]);
                float v1 = celu_f(d[1] + sBias[160 + col + 1]);
                float v2 = celu_f(d[2] + sBias[160 + col]);
                float v3 = celu_f(d[3] + sBias[160 + col + 1]);
                *(uint32_t*)(smem + H1_OFF + row0 * 272 + col * 2)       = pack2h(v0, v1);
                *(uint32_t*)(smem + H1_OFF + (row0 + 8) * 272 + col * 2) = pack2h(v2, v3);
            }
        }

        if (half == 0) {   // swap in W1 half 1
            __syncthreads();
            const uint4* src = g_W1img[t][1];
            for (int i = tid; i < 1344; i += 256) cp16(sb + WB_OFF + i * 16, src + i);
            CP_COMMIT();
            CP_WAIT(0);
            __syncthreads();
        }
    }
    __syncthreads();

    // stage W2 into WB
    {
        const uint4* src = g_W2img[t];
        for (int i = tid; i < 1632; i += 256) cp16(sb + WB_OFF + i * 16, src + i);
        CP_COMMIT();
        CP_WAIT(0);
    }
    __syncthreads();

    // ===================== LAYER 2: 128 -> 96 (+ fused layer 3) =====================
    float acc2[2][3][4];
    #pragma unroll
    for (int mt = 0; mt < 2; mt++)
        #pragma unroll
        for (int nt = 0; nt < 3; nt++)
            #pragma unroll
            for (int q = 0; q < 4; q++) acc2[mt][nt][q] = 0.f;

    const uint32_t aH1 = sb + H1_OFF + (mb + arow) * 272 + akb;
    const uint32_t bA2 = sb + WB_OFF + (nww * 24 + brow) * 272 + bkb;           // n16
    const uint32_t bC2 = sb + WB_OFF + (nww * 24 + 16 + brow2) * 272 + bkb2;     // n8

    {
        uint32_t Ab[2][2][4], Bb[2][4], Cb[2][2];
        ldm_x4(Ab[0][0], aH1);
        ldm_x4(Ab[0][1], aH1 + 16 * 272);
        ldm_x4(Bb[0], bA2);
        ldm_x2(Cb[0], bC2);
        #pragma unroll
        for (int ks = 0; ks < 8; ks++) {
            const int cur = ks & 1;
            if (ks < 7) {
                const uint32_t kb2 = (ks + 1) * 32;
                ldm_x4(Ab[cur ^ 1][0], aH1 + kb2);
                ldm_x4(Ab[cur ^ 1][1], aH1 + 16 * 272 + kb2);
                ldm_x4(Bb[cur ^ 1], bA2 + kb2);
                ldm_x2(Cb[cur ^ 1], bC2 + kb2);
            }
            #pragma unroll
            for (int mt = 0; mt < 2; mt++) {
                mma_fp16(acc2[mt][0], Ab[cur][mt], Bb[cur]);
                mma_fp16(acc2[mt][1], Ab[cur][mt], Bb[cur] + 2);
                mma_fp16(acc2[mt][2], Ab[cur][mt], Cb[cur]);
            }
        }
    }

    // layer-3 fused epilogue: e[row] = b3 + sum_col celu(x+b2[col]) * w3[col]
    {
        float part[2][2] = {{0.f, 0.f}, {0.f, 0.f}};
        #pragma unroll
        for (int mt = 0; mt < 2; mt++)
            #pragma unroll
            for (int nt = 0; nt < 3; nt++) {
                int col = nww * 24 + nt * 8 + 2 * (lane & 3);
                float* d = acc2[mt][nt];
                part[mt][0] += celu_f(d[0] + sBias[288 + col]) * sBias[384 + col]
                             + celu_f(d[1] + sBias[288 + col + 1]) * sBias[384 + col + 1];
                part[mt][1] += celu_f(d[2] + sBias[288 + col]) * sBias[384 + col]
                             + celu_f(d[3] + sBias[288 + col + 1]) * sBias[384 + col + 1];
            }
        #pragma unroll
        for (int mt = 0; mt < 2; mt++)
            #pragma unroll
            for (int h = 0; h < 2; h++) {
                part[mt][h] += __shfl_xor_sync(0xffffffffu, part[mt][h], 1);
                part[mt][h] += __shfl_xor_sync(0xffffffffu, part[mt][h], 2);
            }
        if ((lane & 3) == 0) {
            #pragma unroll
            for (int mt = 0; mt < 2; mt++)
                #pragma unroll
                for (int h = 0; h < 2; h++) {
                    int row = mb + mt * 16 + h * 8 + (lane >> 2);
                    atomicAdd(&sE[row], part[mt][h]);
                }
        }
    }
    __syncthreads();
    if (tid < TILE) {
        int gi = sIdx[tid];
        if (gi >= 0) g_atom_e[gi] = sE[tid] + sBias[480];
    }
}

// ---------------- launch 5: output assembly ----------------
__global__ void k_finalize(const int* __restrict__ sp,
                           float* __restrict__ out_head,
                           float* __restrict__ out_e)
{
    int b  = blockIdx.x;
    int tx = threadIdx.x;
    int i  = b * NA + tx;
    float e = g_atom_e[i];
    if (out_head) out_head[i] = (float)get_sp(sp, i, g_is64);
    #pragma unroll
    for (int o = 16; o > 0; o >>= 1) e += __shfl_down_sync(0xffffffffu, e, o);
    __shared__ float s2[2];
    if ((tx & 31) == 0) s2[tx >> 5] = e;
    __syncthreads();
    if (tx == 0) out_e[b] = s2[0] + s2[1];
}

extern "C" void kernel_launch(void* const* d_in, const int* in_sizes, int n_in,
                              void* d_out, int out_size)
{
    const int*   sp  = (const int*)d_in[0];
    const float* aev = (const float*)d_in[1];
    const float* W0 = (const float*)d_in[2];
    const float* b0 = (const float*)d_in[3];
    const float* W1 = (const float*)d_in[4];
    const float* b1 = (const float*)d_in[5];
    const float* W2 = (const float*)d_in[6];
    const float* b2 = (const float*)d_in[7];
    const float* W3 = (const float*)d_in[8];
    const float* b3 = (const float*)d_in[9];

    float* out = (float*)d_out;
    float* out_head;
    float* out_e;
    if (out_size == NB) { out_head = nullptr; out_e = out; }
    else                { out_head = out;     out_e = out + (out_size - NB); }

    k_detect    <<<1, 32>>>(sp);
    k_count_prep<<<CP_GRID, 256>>>(sp, W0, W1, W2);
    k_scatter   <<<NATOMS / 256, 256>>>(sp);

    cudaFuncSetAttribute(k_mlp_tc, cudaFuncAttributeMaxDynamicSharedMemorySize, SM_TOTAL);
    k_mlp_tc<<<MAXTILES, 256, SM_TOTAL>>>(aev, b0, b1, b2, W3, b3);

    k_finalize<<<NB, NA>>>(sp, out_head, out_e);
}

// round 10
// speedup vs baseline: 7.6269x; 1.1488x over previous
#include <cuda_runtime.h>
#include <cuda_fp16.h>
#include <cstdint>

// ---------------- problem constants ----------------
#define NB      2048
#define NA      64
#define NATOMS  (NB*NA)
#define AEV     384
#define N0      160
#define N1      128
#define N2      96
#define NTYPES  4
#define TILE    64
#define MAXTILES 2056

// ---------------- device scratch ----------------
__device__ int   g_is64;
__device__ int   g_counts[NTYPES];
__device__ int   g_cursor[NTYPES];
__device__ int   g_perm[NATOMS];

// fp16 weight images, [n][k] layout, padded strides (bytes): W0 208, W1 336, W2 272
__device__ uint4 g_W0img[NTYPES][4][2080];   // per 96-K chunk: 160*208 B
__device__ uint4 g_W1img[NTYPES][2][1344];   // per 64-N half:  64*336 B (K=160)
__device__ uint4 g_W2img[NTYPES][1632];      // 96*272 B (K=128)

__device__ __forceinline__ float celu_f(float x) {
    return x > 0.f ? x : 0.1f * (__expf(10.f * x) - 1.f);
}
// packed CELU on half2 (exp-arg clamped to <=0 so positive branch is exact pass-through)
__device__ __forceinline__ __half2 celu_h2(__half2 x) {
    const __half2 ZERO  = __float2half2_rn(0.f);
    const __half2 ONE   = __float2half2_rn(1.f);
    const __half2 TEN   = __float2half2_rn(10.f);
    const __half2 TENTH = __float2half2_rn(0.1f);
    __half2 xa  = __hmin2(x, ZERO);
    __half2 ex  = h2exp(__hmul2(xa, TEN));
    __half2 neg = __hmul2(__hsub2(ex, ONE), TENTH);
    __half2 m   = __hgt2(x, ZERO);                 // 1.0 where x>0
    return __hfma2(m, __hsub2(x, neg), neg);       // m*(x-neg)+neg
}
__device__ __forceinline__ int get_sp(const int* __restrict__ raw, int i, int is64) {
    return is64 ? raw[2 * i] : raw[i];
}
__device__ __forceinline__ uint32_t pack2h(float a, float b) {
    __half ha = __float2half_rn(a), hb = __float2half_rn(b);
    return (uint32_t)__half_as_ushort(ha) | ((uint32_t)__half_as_ushort(hb) << 16);
}
__device__ __forceinline__ uint32_t smem_u32(const void* p) {
    uint32_t a;
    asm("{ .reg .u64 t; cvta.to.shared.u64 t, %1; cvt.u32.u64 %0, t; }" : "=r"(a) : "l"(p));
    return a;
}
__device__ __forceinline__ void ldm_x4(uint32_t* r, uint32_t addr) {
    asm volatile("ldmatrix.sync.aligned.m8n8.x4.shared.b16 {%0,%1,%2,%3}, [%4];"
                 : "=r"(r[0]), "=r"(r[1]), "=r"(r[2]), "=r"(r[3]) : "r"(addr));
}
__device__ __forceinline__ void ldm_x2(uint32_t* r, uint32_t addr) {
    asm volatile("ldmatrix.sync.aligned.m8n8.x2.shared.b16 {%0,%1}, [%2];"
                 : "=r"(r[0]), "=r"(r[1]) : "r"(addr));
}
__device__ __forceinline__ void mma_fp16(float* d, const uint32_t* a, const uint32_t* b) {
    asm volatile(
        "mma.sync.aligned.m16n8k16.row.col.f32.f16.f16.f32 "
        "{%0,%1,%2,%3},{%4,%5,%6,%7},{%8,%9},{%0,%1,%2,%3};"
        : "+f"(d[0]), "+f"(d[1]), "+f"(d[2]), "+f"(d[3])
        : "r"(a[0]), "r"(a[1]), "r"(a[2]), "r"(a[3]), "r"(b[0]), "r"(b[1]));
}
__device__ __forceinline__ void cp16(uint32_t s, const void* g) {
    asm volatile("cp.async.cg.shared.global [%0], [%1], 16;" :: "r"(s), "l"(g) : "memory");
}
#define CP_COMMIT() asm volatile("cp.async.commit_group;" ::: "memory")
#define CP_WAIT(n)  asm volatile("cp.async.wait_group %0;" :: "n"(n) : "memory")

// ---------------- launch 1: dtype probe + reset ----------------
__global__ void k_detect(const int* __restrict__ sp_raw) {
    if (threadIdx.x == 0) {
        int odd_nonzero = 0;
        #pragma unroll
        for (int i = 1; i < 64; i += 2) odd_nonzero |= (sp_raw[i] != 0);
        g_is64 = odd_nonzero ? 0 : 1;
    }
    if (threadIdx.x < NTYPES) { g_counts[threadIdx.x] = 0; g_cursor[threadIdx.x] = 0; }
}

// ---------------- launch 2: count + weight prep (fused) ----------------
#define PREP_W0 122880
#define PREP_W1 40960
#define PREP_W2 24576
#define PREP_TOTAL (PREP_W0 + PREP_W1 + PREP_W2)
#define CP_GRID ((PREP_TOTAL + 255) / 256)

__global__ void k_count_prep(const int* __restrict__ sp,
                             const float* __restrict__ W0, const float* __restrict__ W1,
                             const float* __restrict__ W2) {
    int gid = blockIdx.x * blockDim.x + threadIdx.x;

    __shared__ int c[NTYPES];
    if (threadIdx.x < NTYPES) c[threadIdx.x] = 0;
    __syncthreads();
    if (gid < NATOMS) {
        int t = get_sp(sp, gid, g_is64);
        if ((unsigned)t < NTYPES) atomicAdd(&c[t], 1);
    }
    __syncthreads();
    if (threadIdx.x < NTYPES && c[threadIdx.x]) atomicAdd(&g_counts[threadIdx.x], c[threadIdx.x]);

    int idx = gid;
    if (idx < PREP_W0) {
        int t = idx / 30720, r = idx % 30720;
        int cc = r / 7680;  r %= 7680;
        int n = r / 48, j = r % 48;
        int k0 = cc * 96 + 2 * j;
        float v0 = W0[((size_t)t * AEV + k0)     * N0 + n];
        float v1 = W0[((size_t)t * AEV + k0 + 1) * N0 + n];
        *(uint32_t*)((char*)g_W0img[t][cc] + n * 208 + j * 4) = pack2h(v0, v1);
    } else if (idx < PREP_W0 + PREP_W1) {
        int i2 = idx - PREP_W0;
        int t = i2 / 10240, r = i2 % 10240;
        int h = r / 5120;  r %= 5120;
        int n = r / 80, j = r % 80;
        int k0 = 2 * j;
        float v0 = W1[((size_t)t * N0 + k0)     * N1 + h * 64 + n];
        float v1 = W1[((size_t)t * N0 + k0 + 1) * N1 + h * 64 + n];
        *(uint32_t*)((char*)g_W1img[t][h] + n * 336 + j * 4) = pack2h(v0, v1);
    } else if (idx < PREP_TOTAL) {
        int i3 = idx - PREP_W0 - PREP_W1;
        int t = i3 / 6144, r = i3 % 6144;
        int n = r / 64, j = r % 64;
        int k0 = 2 * j;
        float v0 = W2[((size_t)t * N1 + k0)     * N2 + n];
        float v1 = W2[((size_t)t * N1 + k0 + 1) * N2 + n];
        *(uint32_t*)((char*)g_W2img[t] + n * 272 + j * 4) = pack2h(v0, v1);
    }
}

// ---------------- launch 3: scatter + output-head + out_e zero ----------------
__global__ void k_scatter(const int* __restrict__ sp,
                          float* __restrict__ out_head,
                          float* __restrict__ out_e) {
    __shared__ int soff[NTYPES];
    __shared__ int base[NTYPES];
    __shared__ int lc[NTYPES];
    if (threadIdx.x == 0) {
        int o = 0;
        #pragma unroll
        for (int t = 0; t < NTYPES; t++) { soff[t] = o; o += g_counts[t]; }
    }
    if (threadIdx.x < NTYPES) lc[threadIdx.x] = 0;
    __syncthreads();
    int i = blockIdx.x * blockDim.x + threadIdx.x;
    if (i < NB) out_e[i] = 0.f;
    int t = -1, r = 0;
    if (i < NATOMS) {
        int tv = get_sp(sp, i, g_is64);
        if (out_head) out_head[i] = (float)tv;
        if ((unsigned)tv < NTYPES) { t = tv; r = atomicAdd(&lc[t], 1); }
    }
    __syncthreads();
    if (threadIdx.x < NTYPES)
        base[threadIdx.x] = lc[threadIdx.x] ? atomicAdd(&g_cursor[threadIdx.x], lc[threadIdx.x]) : 0;
    __syncthreads();
    if (t >= 0) g_perm[soff[t] + base[t] + r] = i;
}

// ---------------- launch 4: fused MLP (64-atom tiles, 2Mx4N warps, A-pipelined) ----------------
#define BIAS_OFF 0
#define SIDX_OFF 1936
#define WB_OFF   2560
#define X_OFF    35840
#define H1_OFF   35840
#define H0_OFF   53248
#define SM_TOTAL 74752

__global__ __launch_bounds__(256, 3)
void k_mlp_tc(const float* __restrict__ aev,
              const float* __restrict__ b0, const float* __restrict__ b1,
              const float* __restrict__ b2, const float* __restrict__ W3,
              const float* __restrict__ b3,
              float* __restrict__ out_e)
{
    // derive this CTA's tile (type, start, len) from g_counts
    int t = -1, gstart = 0, len = 0;
    {
        int rem = blockIdx.x, off = 0;
        #pragma unroll
        for (int tt = 0; tt < NTYPES; tt++) {
            int cc = g_counts[tt];
            int ntl = (cc + TILE - 1) / TILE;
            if (t < 0) {
                if (rem < ntl) {
                    t = tt;
                    gstart = off + rem * TILE;
                    int l = cc - rem * TILE;
                    len = l < TILE ? l : TILE;
                } else rem -= ntl;
            }
            off += cc;
        }
    }
    if (t < 0) return;

    extern __shared__ char smem[];
    const uint32_t sb = smem_u32(smem);
    float* sBias = (float*)(smem + BIAS_OFF);
    int*   sIdx  = (int*)(smem + SIDX_OFF);

    const int tid  = threadIdx.x;
    const int lane = tid & 31;
    const int w    = tid >> 5;
    const int mw   = w & 1;         // M group (0/1)
    const int nww  = w >> 1;        // N group (0..3)
    const int mb   = mw * 32;

    if (tid < TILE) sIdx[tid] = (tid < len) ? g_perm[gstart + tid] : -1;
    for (int i = tid; i < N0; i += 256) sBias[i] = b0[t * N0 + i];
    for (int i = tid; i < N1; i += 256) sBias[160 + i] = b1[t * N1 + i];
    for (int i = tid; i < N2; i += 256) { sBias[288 + i] = b2[t * N2 + i]; sBias[384 + i] = W3[t * N2 + i]; }
    if (tid == 0) sBias[480] = b3[t];

    // prefetch W0 chunk 0
    {
        const uint4* src = g_W0img[t][0];
        for (int i = tid; i < 2080; i += 256) cp16(sb + WB_OFF + i * 16, src + i);
        CP_COMMIT();
    }
    __syncthreads();

    // lane offsets for ldmatrix
    const int arow  = (lane & 7) + (lane & 8);
    const int akb   = (lane & 16) ? 16 : 0;
    const int brow  = (lane & 7) + ((lane & 16) ? 8 : 0);
    const int bkb   = (lane & 8) ? 16 : 0;
    const int brow2 = (lane & 7);               // x2 B (n8k16)
    const int bkb2  = (lane & 8) ? 16 : 0;

    // ===================== LAYER 0: 384 -> 160 =====================
    float acc0[2][5][4];
    #pragma unroll
    for (int mt = 0; mt < 2; mt++)
        #pragma unroll
        for (int nt = 0; nt < 5; nt++)
            #pragma unroll
            for (int q = 0; q < 4; q++) acc0[mt][nt][q] = 0.f;

    const uint32_t aX  = sb + X_OFF + (mb + arow) * 208 + akb;
    const uint32_t bA0 = sb + WB_OFF + (nww * 40 + brow) * 208 + bkb;           // n16 @ +0
    const uint32_t bB0 = bA0 + 16 * 208;                                         // n16 @ +16
    const uint32_t bC0 = sb + WB_OFF + (nww * 40 + 32 + brow2) * 208 + bkb2;     // n8  @ +32

    for (int c = 0; c < 4; c++) {
        // stage X chunk c: row = tid/4 (0..63), 24 cols per quarter-thread
        {
            int row  = tid >> 2;
            int col0 = (tid & 3) * 24;
            int gi   = sIdx[row];
            const float4* src = (const float4*)(aev + (size_t)(gi < 0 ? 0 : gi) * AEV + c * 96 + col0);
            char* dx = smem + X_OFF + row * 208 + col0 * 2;
            #pragma unroll
            for (int i = 0; i < 6; i++) {
                float4 v = (gi >= 0) ? src[i] : make_float4(0.f, 0.f, 0.f, 0.f);
                *(__half2*)(dx + i * 8)     = __floats2half2_rn(v.x, v.y);
                *(__half2*)(dx + i * 8 + 4) = __floats2half2_rn(v.z, v.w);
            }
        }
        CP_WAIT(0);
        __syncthreads();          // W0 chunk + X ready

        uint32_t Ab[2][2][4];
        ldm_x4(Ab[0][0], aX);
        ldm_x4(Ab[0][1], aX + 16 * 208);
        #pragma unroll
        for (int ks = 0; ks < 6; ks++) {
            const uint32_t kb = ks * 32;
            const int cur = ks & 1;
            uint32_t B0[4], B1[4], B2[2];
            ldm_x4(B0, bA0 + kb);
            ldm_x4(B1, bB0 + kb);
            ldm_x2(B2, bC0 + kb);
            if (ks < 5) {         // prefetch A for next ks
                ldm_x4(Ab[cur ^ 1][0], aX + kb + 32);
                ldm_x4(Ab[cur ^ 1][1], aX + 16 * 208 + kb + 32);
            }
            #pragma unroll
            for (int mt = 0; mt < 2; mt++) {
                mma_fp16(acc0[mt][0], Ab[cur][mt], B0);
                mma_fp16(acc0[mt][1], Ab[cur][mt], B0 + 2);
                mma_fp16(acc0[mt][2], Ab[cur][mt], B1);
                mma_fp16(acc0[mt][3], Ab[cur][mt], B1 + 2);
                mma_fp16(acc0[mt][4], Ab[cur][mt], B2);
            }
        }
        __syncthreads();          // all reads of X/WB done before overwrite

        if (c < 3) {
            const uint4* src = g_W0img[t][c + 1];
            for (int i = tid; i < 2080; i += 256) cp16(sb + WB_OFF + i * 16, src + i);
            CP_COMMIT();
        }
    }

    // prefetch W1 half 0 into WB
    {
        const uint4* src = g_W1img[t][0];
        for (int i = tid; i < 1344; i += 256) cp16(sb + WB_OFF + i * 16, src + i);
        CP_COMMIT();
    }

    // epilogue 0 -> H0 (stride 336), packed celu
    #pragma unroll
    for (int mt = 0; mt < 2; mt++) {
        int row0 = mb + mt * 16 + (lane >> 2);
        #pragma unroll
        for (int nt = 0; nt < 5; nt++) {
            int col = nww * 40 + nt * 8 + 2 * (lane & 3);
            float* d = acc0[mt][nt];
            __half2 v01 = celu_h2(__floats2half2_rn(d[0] + sBias[col], d[1] + sBias[col + 1]));
            __half2 v23 = celu_h2(__floats2half2_rn(d[2] + sBias[col], d[3] + sBias[col + 1]));
            *(__half2*)(smem + H0_OFF + row0 * 336 + col * 2)       = v01;
            *(__half2*)(smem + H0_OFF + (row0 + 8) * 336 + col * 2) = v23;
        }
    }
    CP_WAIT(0);
    __syncthreads();

    // ===================== LAYER 1: 160 -> 128 (two 64-N halves) =====================
    const uint32_t aH0 = sb + H0_OFF + (mb + arow) * 336 + akb;
    const uint32_t bW1 = sb + WB_OFF + (nww * 16 + brow) * 336 + bkb;   // n16 per warp per half

    for (int half = 0; half < 2; half++) {
        float acc1[2][2][4];
        #pragma unroll
        for (int mt = 0; mt < 2; mt++)
            #pragma unroll
            for (int nt = 0; nt < 2; nt++)
                #pragma unroll
                for (int q = 0; q < 4; q++) acc1[mt][nt][q] = 0.f;

        uint32_t Ab[2][2][4], Bb[2][4];
        ldm_x4(Ab[0][0], aH0);
        ldm_x4(Ab[0][1], aH0 + 16 * 336);
        ldm_x4(Bb[0], bW1);
        #pragma unroll
        for (int ks = 0; ks < 10; ks++) {
            const int cur = ks & 1;
            if (ks < 9) {
                const uint32_t kb2 = (ks + 1) * 32;
                ldm_x4(Ab[cur ^ 1][0], aH0 + kb2);
                ldm_x4(Ab[cur ^ 1][1], aH0 + 16 * 336 + kb2);
                ldm_x4(Bb[cur ^ 1], bW1 + kb2);
            }
            #pragma unroll
            for (int mt = 0; mt < 2; mt++) {
                mma_fp16(acc1[mt][0], Ab[cur][mt], Bb[cur]);
                mma_fp16(acc1[mt][1], Ab[cur][mt], Bb[cur] + 2);
            }
        }

        // epilogue 1 -> H1 cols [half*64 + nww*16, +16) (stride 272), packed celu
        #pragma unroll
        for (int mt = 0; mt < 2; mt++) {
            int row0 = mb + mt * 16 + (lane >> 2);
            #pragma unroll
            for (int nt = 0; nt < 2; nt++) {
                int col = half * 64 + nww * 16 + nt * 8 + 2 * (lane & 3);
                float* d = acc1[mt][nt];
                __half2 v01 = celu_h2(__floats2half2_rn(d[0] + sBias[160 + col], d[1] + sBias[160 + col + 1]));
                __half2 v23 = celu_h2(__floats2half2_rn(d[2] + sBias[160 + col], d[3] + sBias[160 + col + 1]));
                *(__half2*)(smem + H1_OFF + row0 * 272 + col * 2)       = v01;
                *(__half2*)(smem + H1_OFF + (row0 + 8) * 272 + col * 2) = v23;
            }
        }

        if (half == 0) {   // swap in W1 half 1
            __syncthreads();
            const uint4* src = g_W1img[t][1];
            for (int i = tid; i < 1344; i += 256) cp16(sb + WB_OFF + i * 16, src + i);
            CP_COMMIT();
            CP_WAIT(0);
            __syncthreads();
        }
    }
    __syncthreads();

    // stage W2 into WB
    {
        const uint4* src = g_W2img[t];
        for (int i = tid; i < 1632; i += 256) cp16(sb + WB_OFF + i * 16, src + i);
        CP_COMMIT();
        CP_WAIT(0);
    }
    __syncthreads();

    // ===================== LAYER 2: 128 -> 96 (+ fused layers 3 & reduce) =====================
    float acc2[2][3][4];
    #pragma unroll
    for (int mt = 0; mt < 2; mt++)
        #pragma unroll
        for (int nt = 0; nt < 3; nt++)
            #pragma unroll
            for (int q = 0; q < 4; q++) acc2[mt][nt][q] = 0.f;

    const uint32_t aH1 = sb + H1_OFF + (mb + arow) * 272 + akb;
    const uint32_t bA2 = sb + WB_OFF + (nww * 24 + brow) * 272 + bkb;           // n16
    const uint32_t bC2 = sb + WB_OFF + (nww * 24 + 16 + brow2) * 272 + bkb2;     // n8

    {
        uint32_t Ab[2][2][4], Bb[2][4], Cb[2][2];
        ldm_x4(Ab[0][0], aH1);
        ldm_x4(Ab[0][1], aH1 + 16 * 272);
        ldm_x4(Bb[0], bA2);
        ldm_x2(Cb[0], bC2);
        #pragma unroll
        for (int ks = 0; ks < 8; ks++) {
            const int cur = ks & 1;
            if (ks < 7) {
                const uint32_t kb2 = (ks + 1) * 32;
                ldm_x4(Ab[cur ^ 1][0], aH1 + kb2);
                ldm_x4(Ab[cur ^ 1][1], aH1 + 16 * 272 + kb2);
                ldm_x4(Bb[cur ^ 1], bA2 + kb2);
                ldm_x2(Cb[cur ^ 1], bC2 + kb2);
            }
            #pragma unroll
            for (int mt = 0; mt < 2; mt++) {
                mma_fp16(acc2[mt][0], Ab[cur][mt], Bb[cur]);
                mma_fp16(acc2[mt][1], Ab[cur][mt], Bb[cur] + 2);
                mma_fp16(acc2[mt][2], Ab[cur][mt], Cb[cur]);
            }
        }
    }

    // layer-3 + molecule reduce: atomicAdd per-atom contribution directly into out_e
    {
        float part[2][2] = {{0.f, 0.f}, {0.f, 0.f}};
        #pragma unroll
        for (int mt = 0; mt < 2; mt++)
            #pragma unroll
            for (int nt = 0; nt < 3; nt++) {
                int col = nww * 24 + nt * 8 + 2 * (lane & 3);
                float* d = acc2[mt][nt];
                part[mt][0] += celu_f(d[0] + sBias[288 + col]) * sBias[384 + col]
                             + celu_f(d[1] + sBias[288 + col + 1]) * sBias[384 + col + 1];
                part[mt][1] += celu_f(d[2] + sBias[288 + col]) * sBias[384 + col]
                             + celu_f(d[3] + sBias[288 + col + 1]) * sBias[384 + col + 1];
            }
        #pragma unroll
        for (int mt = 0; mt < 2; mt++)
            #pragma unroll
            for (int h = 0; h < 2; h++) {
                part[mt][h] += __shfl_xor_sync(0xffffffffu, part[mt][h], 1);
                part[mt][h] += __shfl_xor_sync(0xffffffffu, part[mt][h], 2);
            }
        if ((lane & 3) == 0) {
            #pragma unroll
            for (int mt = 0; mt < 2; mt++)
                #pragma unroll
                for (int h = 0; h < 2; h++) {
                    int row = mb + mt * 16 + h * 8 + (lane >> 2);
                    int gi  = sIdx[row];
                    if (gi >= 0) {
                        float v = part[mt][h] + (nww == 0 ? sBias[480] : 0.f);  // b3 once per atom
                        atomicAdd(out_e + (gi >> 6), v);
                    }
                }
        }
    }
}

extern "C" void kernel_launch(void* const* d_in, const int* in_sizes, int n_in,
                              void* d_out, int out_size)
{
    const int*   sp  = (const int*)d_in[0];
    const float* aev = (const float*)d_in[1];
    const float* W0 = (const float*)d_in[2];
    const float* b0 = (const float*)d_in[3];
    const float* W1 = (const float*)d_in[4];
    const float* b1 = (const float*)d_in[5];
    const float* W2 = (const float*)d_in[6];
    const float* b2 = (const float*)d_in[7];
    const float* W3 = (const float*)d_in[8];
    const float* b3 = (const float*)d_in[9];

    float* out = (float*)d_out;
    float* out_head;
    float* out_e;
    if (out_size == NB) { out_head = nullptr; out_e = out; }
    else                { out_head = out;     out_e = out + (out_size - NB); }

    k_detect    <<<1, 32>>>(sp);
    k_count_prep<<<CP_GRID, 256>>>(sp, W0, W1, W2);
    k_scatter   <<<NATOMS / 256, 256>>>(sp, out_head, out_e);

    cudaFuncSetAttribute(k_mlp_tc, cudaFuncAttributeMaxDynamicSharedMemorySize, SM_TOTAL);
    k_mlp_tc<<<MAXTILES, 256, SM_TOTAL>>>(aev, b0, b1, b2, W3, b3, out_e);
}